// round 9
// baseline (speedup 1.0000x reference)
#include <cuda_runtime.h>
#include <cstdint>

// Problem constants
#define S_LEN    2048
#define DMODEL   1024
#define NHEADS   16
#define DK       64
#define BATCH    2
#define M_TOTAL  (BATCH * S_LEN)   // 4096

// Scratch (allocation-free rule: __device__ globals)
__device__ float g_q[BATCH * NHEADS * S_LEN * DK];     // (B,H,S,dk) tf32-rounded
__device__ float g_k[BATCH * NHEADS * S_LEN * DK];
__device__ float g_v[BATCH * NHEADS * S_LEN * DK];
__device__ float g_att[BATCH * S_LEN * DMODEL];        // (B,S,D) tf32-rounded
__device__ float g_round[8 * 1024 * 1024];             // rounded x + 4 weights

// ---------------------------------------------------------------------------
// Helpers
// ---------------------------------------------------------------------------
__device__ __forceinline__ uint32_t smem_u32(const void* p) {
    uint32_t a;
    asm("{ .reg .u64 t; cvta.to.shared.u64 t, %1; cvt.u32.u64 %0, t; }"
        : "=r"(a) : "l"(p));
    return a;
}

__device__ __forceinline__ void cp_async16(uint32_t s, const void* g) {
    asm volatile("cp.async.cg.shared.global [%0], [%1], 16;" :: "r"(s), "l"(g));
}
#define CP_COMMIT() asm volatile("cp.async.commit_group;" ::: "memory")
#define CP_WAIT(n)  asm volatile("cp.async.wait_group %0;" :: "n"(n) : "memory")

__device__ __forceinline__ float round_tf32(float v) {
    uint32_t u;
    asm("cvt.rna.tf32.f32 %0, %1;" : "=r"(u) : "f"(v));
    return __uint_as_float(u);
}

// D(16x8) += A(16x8,row) * B(8x8,col)  -- tf32, fp32 accum
__device__ __forceinline__ void mma_tf32(float* d,
                                         uint32_t a0, uint32_t a1, uint32_t a2, uint32_t a3,
                                         uint32_t b0, uint32_t b1) {
    asm volatile(
        "mma.sync.aligned.m16n8k8.row.col.f32.tf32.tf32.f32 "
        "{%0,%1,%2,%3}, {%4,%5,%6,%7}, {%8,%9}, {%0,%1,%2,%3};"
        : "+f"(d[0]), "+f"(d[1]), "+f"(d[2]), "+f"(d[3])
        : "r"(a0), "r"(a1), "r"(a2), "r"(a3), "r"(b0), "r"(b1));
}

// ldmatrix x4: one instr loads four 8x8-b16 tiles (= four 8x4-f32 tiles)
__device__ __forceinline__ void ldsm4(uint32_t* r, uint32_t addr) {
    asm volatile("ldmatrix.sync.aligned.m8n8.x4.shared.b16 {%0,%1,%2,%3}, [%4];"
        : "=r"(r[0]), "=r"(r[1]), "=r"(r[2]), "=r"(r[3]) : "r"(addr));
}

// ---------------------------------------------------------------------------
// Single fused tf32 rounding pass over x + 4 weights.
// ---------------------------------------------------------------------------
__global__ __launch_bounds__(256) void round_all_kernel(
    const float* __restrict__ x,
    const float* __restrict__ wq, const float* __restrict__ wk,
    const float* __restrict__ wv, const float* __restrict__ wo,
    float* __restrict__ xr,
    float* __restrict__ wqr, float* __restrict__ wkr,
    float* __restrict__ wvr, float* __restrict__ wor)
{
    const int bidx = blockIdx.x;
    const float* src;
    float* dst;
    int off;
    if (bidx < 4096) { src = x; dst = xr; off = bidx; }
    else {
        const int i = (bidx - 4096) >> 10;
        off = (bidx - 4096) & 1023;
        src = (i == 0) ? wq : (i == 1) ? wk : (i == 2) ? wv : wo;
        dst = (i == 0) ? wqr : (i == 1) ? wkr : (i == 2) ? wvr : wor;
    }
    const int idx = off * 256 + threadIdx.x;
    float4 v = ((const float4*)src)[idx];
    float4 o;
    o.x = round_tf32(v.x); o.y = round_tf32(v.y);
    o.z = round_tf32(v.z); o.w = round_tf32(v.w);
    ((float4*)dst)[idx] = o;
}

// ---------------------------------------------------------------------------
// tf32 mma.sync GEMM (unchanged from round 7): tile 256x128, warp 64x64,
// XOR-swizzled 3-stage cp.async, ldmatrix fragments.
// ---------------------------------------------------------------------------
#define GTM 256
#define GTN 128
#define A_STAGE_F (GTM * 32)                 // 8192 floats = 32KB
#define B_STAGE_F (GTN * 32)                 // 4096 floats = 16KB
#define STG_F     (A_STAGE_F + B_STAGE_F)    // 12288 floats = 48KB
#define GSTAGES   3
#define GEMM_SMEM (GSTAGES * STG_F * (int)sizeof(float))   // 147456

__global__ __launch_bounds__(256, 1) void gemm_tc_kernel(
    const float* __restrict__ A,
    const float* __restrict__ W0, const float* __restrict__ W1, const float* __restrict__ W2,
    float* __restrict__ C0, float* __restrict__ C1, float* __restrict__ C2,
    int scatter)
{
    const float* __restrict__ W = (blockIdx.z == 0) ? W0 : (blockIdx.z == 1) ? W1 : W2;
    float* __restrict__ C       = (blockIdx.z == 0) ? C0 : (blockIdx.z == 1) ? C1 : C2;

    extern __shared__ float sm[];

    const int tid  = threadIdx.x;
    const int wid  = tid >> 5;
    const int lane = tid & 31;
    const int g    = lane >> 2;          // 0..7 row group
    const int t    = lane & 3;           // 0..3 thread-in-group
    const int wm   = wid & 3;            // warp m index (64 rows each)
    const int wn   = wid >> 2;           // warp n index (64 cols each)
    const int nBase = blockIdx.x * GTN;
    const int mBase = blockIdx.y * GTM;

    float acc[4][8][4];
#pragma unroll
    for (int i = 0; i < 4; i++)
#pragma unroll
        for (int j = 0; j < 8; j++)
#pragma unroll
            for (int l = 0; l < 4; l++) acc[i][j][l] = 0.0f;

    const uint32_t smemA0 = smem_u32(sm);

    const int rowA = wm * 64 + (lane & 15);
    const int rowB = wn * 64 + (lane & 7) + ((lane >> 4) << 3);
    const int c4bitA = lane >> 4;
    const int c4bitB = (lane >> 3) & 1;
    const int lxor   = lane & 7;

    auto issue = [&](int c, int s) {
        const uint32_t st = smemA0 + (uint32_t)(s * STG_F) * 4u;
#pragma unroll
        for (int i = 0; i < 8; i++) {
            const int idx = tid + 256 * i;
            const int r = idx >> 3, c4 = idx & 7;
            const uint32_t off = (uint32_t)(r * 32 + (((c4 ^ (r & 7)) & 7) << 2)) * 4u;
            cp_async16(st + off, A + (size_t)(mBase + r) * DMODEL + c * 32 + c4 * 4);
        }
#pragma unroll
        for (int i = 0; i < 4; i++) {
            const int idx = tid + 256 * i;
            const int r = idx >> 3, c4 = idx & 7;
            const uint32_t off = (uint32_t)(r * 32 + (((c4 ^ (r & 7)) & 7) << 2)) * 4u;
            cp_async16(st + (uint32_t)A_STAGE_F * 4u + off,
                       W + (size_t)(nBase + r) * DMODEL + c * 32 + c4 * 4);
        }
    };

    issue(0, 0); CP_COMMIT();
    issue(1, 1); CP_COMMIT();

    const int NCHUNK = DMODEL / 32;   // 32
    for (int c = 0; c < NCHUNK; c++) {
        CP_WAIT(1);
        __syncthreads();
        if (c + 2 < NCHUNK) issue(c + 2, (c + 2) % GSTAGES);
        CP_COMMIT();

        const uint32_t Ast = smemA0 + (uint32_t)((c % GSTAGES) * STG_F) * 4u;
        const uint32_t Bst = Ast + (uint32_t)A_STAGE_F * 4u;

#pragma unroll
        for (int ks = 0; ks < 4; ks++) {
            const int xa = ((2 * ks + c4bitA) ^ lxor) & 7;
            const int xb = ((2 * ks + c4bitB) ^ lxor) & 7;

            uint32_t a[4][4];
#pragma unroll
            for (int mt = 0; mt < 4; mt++)
                ldsm4(a[mt], Ast + (uint32_t)((rowA + mt * 16) * 32 + xa * 4) * 4u);

            uint32_t b[4][4];
#pragma unroll
            for (int ntp = 0; ntp < 4; ntp++)
                ldsm4(b[ntp], Bst + (uint32_t)((rowB + ntp * 16) * 32 + xb * 4) * 4u);

#pragma unroll
            for (int mt = 0; mt < 4; mt++)
#pragma unroll
                for (int ntp = 0; ntp < 4; ntp++) {
                    mma_tf32(acc[mt][2 * ntp],     a[mt][0], a[mt][1], a[mt][2], a[mt][3],
                             b[ntp][0], b[ntp][1]);
                    mma_tf32(acc[mt][2 * ntp + 1], a[mt][0], a[mt][1], a[mt][2], a[mt][3],
                             b[ntp][2], b[ntp][3]);
                }
        }
    }

#pragma unroll
    for (int mt = 0; mt < 4; mt++) {
#pragma unroll
        for (int half = 0; half < 2; half++) {
            const int m = mBase + wm * 64 + mt * 16 + g + half * 8;
#pragma unroll
            for (int nt = 0; nt < 8; nt++) {
                const int n = nBase + wn * 64 + nt * 8 + 2 * t;
                float2 v;
                v.x = acc[mt][nt][half * 2 + 0];
                v.y = acc[mt][nt][half * 2 + 1];
                if (scatter) {
                    v.x = round_tf32(v.x); v.y = round_tf32(v.y);
                    const int b = m >> 11, s = m & 2047;
                    const int head = n >> 6, d0 = n & 63;
                    *(float2*)&C[(((size_t)((b << 4) + head) * S_LEN + s) * DK + d0)] = v;
                } else {
                    *(float2*)&C[(size_t)m * DMODEL + n] = v;
                }
            }
        }
    }
}

// ---------------------------------------------------------------------------
// Flash attention: all three fragment streams via ldmatrix, Q in smem panels
// (NOT persistent registers -- avoids the round-8 spill regression):
//  - Q in per-warp XOR-swizzled panels, staged once pre-scaled; ldsm4 per ks
//  - K in XOR-swizzled panels; ldsm4 b-frags
//  - P staged per-warp in swizzled panels; ldsm4 a-frags
//  - V scalar LDS (conflict-free)
// CTA: 256 thr (8 warps), Q block 256 rows (32/warp), kv tile 64, 2 stages.
// ---------------------------------------------------------------------------
#define KPAN_F  2048                  // K panel: 64 rows x 32 floats
#define KST_F   4096                  // K stage (2 panels)
#define VSTR    68
#define VST_F   (64 * VSTR)           // 4352
#define ASTG_F  (KST_F + VST_F)       // 8448 floats per stage
#define SQ_OFF  (2 * ASTG_F)          // 16896
#define SQW_F   2048                  // per-warp Q region (2 panels x 32x32)
#define SP_OFF  (SQ_OFF + 8 * SQW_F)  // 33280
#define SPW_F   2048                  // per-warp P region (2 panels x 32x32)
#define ATTN_F  (SP_OFF + 8 * SPW_F)  // 49664 floats
#define ATTN_SMEM (ATTN_F * (int)sizeof(float))   // 198656 bytes

__global__ __launch_bounds__(256) void attn_kernel(
    const float* __restrict__ Q, const float* __restrict__ K,
    const float* __restrict__ V, float* __restrict__ Oatt)
{
    extern __shared__ float sm[];

    const int tid  = threadIdx.x;
    const int wid  = tid >> 5;
    const int lane = tid & 31;
    const int g    = lane >> 2;
    const int t    = lane & 3;
    const int qb   = blockIdx.x;            // 0..7  (256 rows each)
    const int bh   = blockIdx.y;            // 0..31
    const int b    = bh >> 4;
    const int h    = bh & 15;

    const uint32_t smemB = smem_u32(sm);
    const uint32_t sqw   = smemB + (uint32_t)(SQ_OFF + wid * SQW_F) * 4u;
    const uint32_t spw   = smemB + (uint32_t)(SP_OFF + wid * SPW_F) * 4u;
    float* sQf = sm + SQ_OFF + wid * SQW_F;
    float* sPf = sm + SP_OFF + wid * SPW_F;

    // ---- Stage Q slice (32 rows/warp) into swizzled panels, pre-scaled by 1/8
    {
        const float* Qg = Q + ((size_t)bh * S_LEN + qb * 256 + wid * 32) * DK;
#pragma unroll
        for (int i = 0; i < 16; i++) {
            const int idx = lane + 32 * i;       // 0..511
            const int r = idx >> 4, c4 = idx & 15;
            float4 v = *(const float4*)&Qg[r * DK + c4 * 4];
            v.x *= 0.125f; v.y *= 0.125f; v.z *= 0.125f; v.w *= 0.125f;
            const int off = (c4 >> 3) * 1024 + r * 32 + ((((c4 & 7) ^ (r & 7)) & 7) << 2);
            *(float4*)&sQf[off] = v;
        }
        __syncwarp();
    }

    float o_[2][8][4];
#pragma unroll
    for (int mt = 0; mt < 2; mt++)
#pragma unroll
        for (int nt = 0; nt < 8; nt++)
#pragma unroll
            for (int l = 0; l < 4; l++) o_[mt][nt][l] = 0.0f;
    float mrow[2][2] = {{-1e30f, -1e30f}, {-1e30f, -1e30f}};
    float lrow[2][2] = {{0.0f, 0.0f}, {0.0f, 0.0f}};

    const float* Kg = K + (size_t)bh * S_LEN * DK;
    const float* Vg = V + (size_t)bh * S_LEN * DK;

    // K/V tile loader (K swizzled panels, V padded rows)
    auto issue = [&](int kv, int st) {
        const uint32_t stb = smemB + (uint32_t)(st * ASTG_F) * 4u;
        const float* kS = Kg + (size_t)kv * 64 * DK;
        const float* vS = Vg + (size_t)kv * 64 * DK;
#pragma unroll
        for (int i = 0; i < 4; i++) {
            const int idx = tid + 256 * i;        // 0..1023
            const int r = idx >> 4, c4 = idx & 15;
            const uint32_t koff =
                (uint32_t)((c4 >> 3) * KPAN_F + r * 32 + ((((c4 & 7) ^ (r & 7)) & 7) << 2)) * 4u;
            cp_async16(stb + koff, kS + r * DK + c4 * 4);
            const uint32_t voff = (uint32_t)(KST_F + r * VSTR + c4 * 4) * 4u;
            cp_async16(stb + voff, vS + r * DK + c4 * 4);
        }
    };

    issue(0, 0); CP_COMMIT();

    const int rB  = (lane & 7) + ((lane >> 4) << 3);   // + nt2*16
    const int cbB = (lane >> 3) & 1;
    const int cbA = lane >> 4;
    const int lx  = lane & 7;
    const int rowPbase = lane & 15;                    // + mt*16

    const int NKV = S_LEN / 64;   // 32
    for (int kv = 0; kv < NKV; kv++) {
        CP_WAIT(0);
        __syncthreads();
        if (kv + 1 < NKV) issue(kv + 1, (kv + 1) & 1);
        CP_COMMIT();

        const uint32_t Kst = smemB + (uint32_t)((kv & 1) * ASTG_F) * 4u;
        const float* sV = sm + (kv & 1) * ASTG_F + KST_F;

        // ---- scores S = (Q/8) K^T   (32 x 64 per warp; Q+K via ldmatrix)
        float s_[2][8][4];
#pragma unroll
        for (int mt = 0; mt < 2; mt++)
#pragma unroll
            for (int nt = 0; nt < 8; nt++)
#pragma unroll
                for (int l = 0; l < 4; l++) s_[mt][nt][l] = 0.0f;

#pragma unroll
        for (int ks = 0; ks < 8; ks++) {
            const uint32_t panq = (uint32_t)((ks >> 2) * 1024) * 4u;
            const uint32_t swq  = (uint32_t)((((2 * (ks & 3) + cbA) ^ lx) & 7) << 2) * 4u;
            uint32_t qa2[2][4];
#pragma unroll
            for (int mt = 0; mt < 2; mt++)
                ldsm4(qa2[mt], sqw + panq + (uint32_t)((mt * 16 + rowPbase) * 32) * 4u + swq);

            const uint32_t pan = (uint32_t)((ks >> 2) * KPAN_F) * 4u;
            const uint32_t sw  = (uint32_t)((((2 * (ks & 3) + cbB) ^ lx) & 7) << 2) * 4u;
            uint32_t bb[4][4];
#pragma unroll
            for (int nt2 = 0; nt2 < 4; nt2++)
                ldsm4(bb[nt2], Kst + pan + (uint32_t)((nt2 * 16 + rB) * 32) * 4u + sw);
#pragma unroll
            for (int nt2 = 0; nt2 < 4; nt2++) {
                mma_tf32(s_[0][2 * nt2],     qa2[0][0], qa2[0][1], qa2[0][2], qa2[0][3],
                         bb[nt2][0], bb[nt2][1]);
                mma_tf32(s_[0][2 * nt2 + 1], qa2[0][0], qa2[0][1], qa2[0][2], qa2[0][3],
                         bb[nt2][2], bb[nt2][3]);
                mma_tf32(s_[1][2 * nt2],     qa2[1][0], qa2[1][1], qa2[1][2], qa2[1][3],
                         bb[nt2][0], bb[nt2][1]);
                mma_tf32(s_[1][2 * nt2 + 1], qa2[1][0], qa2[1][1], qa2[1][2], qa2[1][3],
                         bb[nt2][2], bb[nt2][3]);
            }
        }

        // ---- online softmax per m-tile; store P into swizzled panels
#pragma unroll
        for (int mt = 0; mt < 2; mt++) {
            float mx0 = -1e30f, mx1 = -1e30f;
#pragma unroll
            for (int nt = 0; nt < 8; nt++) {
                mx0 = fmaxf(mx0, fmaxf(s_[mt][nt][0], s_[mt][nt][1]));
                mx1 = fmaxf(mx1, fmaxf(s_[mt][nt][2], s_[mt][nt][3]));
            }
            mx0 = fmaxf(mx0, __shfl_xor_sync(0xffffffffu, mx0, 1));
            mx0 = fmaxf(mx0, __shfl_xor_sync(0xffffffffu, mx0, 2));
            mx1 = fmaxf(mx1, __shfl_xor_sync(0xffffffffu, mx1, 1));
            mx1 = fmaxf(mx1, __shfl_xor_sync(0xffffffffu, mx1, 2));

            float mn0 = fmaxf(mrow[mt][0], mx0), mn1 = fmaxf(mrow[mt][1], mx1);
            float al0 = __expf(mrow[mt][0] - mn0), al1 = __expf(mrow[mt][1] - mn1);
            mrow[mt][0] = mn0; mrow[mt][1] = mn1;

            float s0 = 0.0f, s1 = 0.0f;
#pragma unroll
            for (int nt = 0; nt < 8; nt++) {
                s_[mt][nt][0] = __expf(s_[mt][nt][0] - mn0); s0 += s_[mt][nt][0];
                s_[mt][nt][1] = __expf(s_[mt][nt][1] - mn0); s0 += s_[mt][nt][1];
                s_[mt][nt][2] = __expf(s_[mt][nt][2] - mn1); s1 += s_[mt][nt][2];
                s_[mt][nt][3] = __expf(s_[mt][nt][3] - mn1); s1 += s_[mt][nt][3];
            }
            s0 += __shfl_xor_sync(0xffffffffu, s0, 1);
            s0 += __shfl_xor_sync(0xffffffffu, s0, 2);
            s1 += __shfl_xor_sync(0xffffffffu, s1, 1);
            s1 += __shfl_xor_sync(0xffffffffu, s1, 2);
            lrow[mt][0] = lrow[mt][0] * al0 + s0;
            lrow[mt][1] = lrow[mt][1] * al1 + s1;

#pragma unroll
            for (int nt = 0; nt < 8; nt++) {
                o_[mt][nt][0] *= al0; o_[mt][nt][1] *= al0;
                o_[mt][nt][2] *= al1; o_[mt][nt][3] *= al1;
            }

            // P store (tf32-rounded) into swizzled panels
#pragma unroll
            for (int nt = 0; nt < 8; nt++) {
                const int pan = nt >> 2;
                const int grp = 2 * (nt & 3) + (t >> 1);
                const int offw = (2 * t) & 3;
                const int r0 = mt * 16 + g;
                float* d0 = sPf + pan * 1024 + r0 * 32 + (((grp ^ g) & 7) << 2) + offw;
                float2 p01 = make_float2(round_tf32(s_[mt][nt][0]), round_tf32(s_[mt][nt][1]));
                float2 p23 = make_float2(round_tf32(s_[mt][nt][2]), round_tf32(s_[mt][nt][3]));
                *(float2*)d0          = p01;
                *(float2*)(d0 + 256)  = p23;      // row+8: +8*32 floats
            }
        }
        __syncwarp();

        // ---- O += P V  (P a-frags via ldmatrix, V scalar)
#pragma unroll
        for (int kt = 0; kt < 8; kt++) {
            const uint32_t swp = (uint32_t)((((2 * (kt & 3) + cbA) ^ lx) & 7) << 2) * 4u;
            const uint32_t panp = (uint32_t)((kt >> 2) * 1024) * 4u;
            uint32_t ap[2][4];
#pragma unroll
            for (int mt = 0; mt < 2; mt++)
                ldsm4(ap[mt], spw + panp + (uint32_t)((mt * 16 + rowPbase) * 32) * 4u + swp);
#pragma unroll
            for (int nt = 0; nt < 8; nt++) {
                const float* Vr = sV + (kt * 8 + t) * VSTR + nt * 8 + g;
                uint32_t b0 = __float_as_uint(Vr[0]);
                uint32_t b1 = __float_as_uint(Vr[4 * VSTR]);
                mma_tf32(o_[0][nt], ap[0][0], ap[0][1], ap[0][2], ap[0][3], b0, b1);
                mma_tf32(o_[1][nt], ap[1][0], ap[1][1], ap[1][2], ap[1][3], b0, b1);
            }
        }
        __syncwarp();
    }

    // ---- epilogue: normalize, round to tf32, write (B,S,D)
#pragma unroll
    for (int mt = 0; mt < 2; mt++) {
        const float inv0 = 1.0f / lrow[mt][0], inv1 = 1.0f / lrow[mt][1];
        const int row0 = qb * 256 + wid * 32 + mt * 16 + g;
#pragma unroll
        for (int nt = 0; nt < 8; nt++) {
            const int col = h * DK + nt * 8 + 2 * t;
            float2 v0, v1;
            v0.x = round_tf32(o_[mt][nt][0] * inv0); v0.y = round_tf32(o_[mt][nt][1] * inv0);
            v1.x = round_tf32(o_[mt][nt][2] * inv1); v1.y = round_tf32(o_[mt][nt][3] * inv1);
            *(float2*)&Oatt[((size_t)b * S_LEN + row0) * DMODEL + col]     = v0;
            *(float2*)&Oatt[((size_t)b * S_LEN + row0 + 8) * DMODEL + col] = v1;
        }
    }
}

// ---------------------------------------------------------------------------
extern "C" void kernel_launch(void* const* d_in, const int* in_sizes, int n_in,
                              void* d_out, int out_size)
{
    const float* x  = (const float*)d_in[0];
    const float* Wq = (const float*)d_in[1];
    const float* Wk = (const float*)d_in[2];
    const float* Wv = (const float*)d_in[3];
    const float* Wo = (const float*)d_in[4];
    float* out = (float*)d_out;

    float *qp, *kp, *vp, *attp, *rp;
    cudaGetSymbolAddress((void**)&qp,   g_q);
    cudaGetSymbolAddress((void**)&kp,   g_k);
    cudaGetSymbolAddress((void**)&vp,   g_v);
    cudaGetSymbolAddress((void**)&attp, g_att);
    cudaGetSymbolAddress((void**)&rp,   g_round);

    float* xr  = rp;
    float* wqr = rp + 4 * 1024 * 1024;
    float* wkr = rp + 5 * 1024 * 1024;
    float* wvr = rp + 6 * 1024 * 1024;
    float* wor = rp + 7 * 1024 * 1024;

    // 0) single fused tf32 rna pre-rounding of all GEMM inputs
    round_all_kernel<<<8192, 256>>>(x, Wq, Wk, Wv, Wo, xr, wqr, wkr, wvr, wor);

    cudaFuncSetAttribute(gemm_tc_kernel, cudaFuncAttributeMaxDynamicSharedMemorySize,
                         GEMM_SMEM);
    cudaFuncSetAttribute(attn_kernel, cudaFuncAttributeMaxDynamicSharedMemorySize,
                         ATTN_SMEM);

    // 1) Fused QKV projections (tf32 mma), scatter+round to (B,H,S,dk)
    dim3 gQKV(DMODEL / GTN, M_TOTAL / GTM, 3);
    gemm_tc_kernel<<<gQKV, 256, GEMM_SMEM>>>(xr, wqr, wkr, wvr, qp, kp, vp, 1);

    // 2) Flash attention (tf32 mma) -> (B,S,D), rounded
    dim3 gA(S_LEN / 256, BATCH * NHEADS);
    attn_kernel<<<gA, 256, ATTN_SMEM>>>(qp, kp, vp, attp);

    // 3) Output projection (tf32 mma) -> d_out
    dim3 gO(DMODEL / GTN, M_TOTAL / GTM, 1);
    gemm_tc_kernel<<<gO, 256, GEMM_SMEM>>>(attp, wor, wor, wor, out, out, out, 0);
}

// round 10
// speedup vs baseline: 1.0593x; 1.0593x over previous
#include <cuda_runtime.h>
#include <cstdint>

// Problem constants
#define S_LEN    2048
#define DMODEL   1024
#define NHEADS   16
#define DK       64
#define BATCH    2
#define M_TOTAL  (BATCH * S_LEN)   // 4096

// Scratch (allocation-free rule: __device__ globals)
__device__ float g_q[BATCH * NHEADS * S_LEN * DK];     // (B,H,S,dk) tf32-rounded
__device__ float g_k[BATCH * NHEADS * S_LEN * DK];
__device__ float g_v[BATCH * NHEADS * S_LEN * DK];
__device__ float g_att[BATCH * S_LEN * DMODEL];        // (B,S,D) tf32-rounded
__device__ float g_round[8 * 1024 * 1024];             // rounded x + 4 weights

// ---------------------------------------------------------------------------
// Helpers
// ---------------------------------------------------------------------------
__device__ __forceinline__ uint32_t smem_u32(const void* p) {
    uint32_t a;
    asm("{ .reg .u64 t; cvta.to.shared.u64 t, %1; cvt.u32.u64 %0, t; }"
        : "=r"(a) : "l"(p));
    return a;
}

__device__ __forceinline__ void cp_async16(uint32_t s, const void* g) {
    asm volatile("cp.async.cg.shared.global [%0], [%1], 16;" :: "r"(s), "l"(g));
}
#define CP_COMMIT() asm volatile("cp.async.commit_group;" ::: "memory")
#define CP_WAIT(n)  asm volatile("cp.async.wait_group %0;" :: "n"(n) : "memory")

__device__ __forceinline__ float round_tf32(float v) {
    uint32_t u;
    asm("cvt.rna.tf32.f32 %0, %1;" : "=r"(u) : "f"(v));
    return __uint_as_float(u);
}

// D(16x8) += A(16x8,row) * B(8x8,col)  -- tf32, fp32 accum
__device__ __forceinline__ void mma_tf32(float* d,
                                         uint32_t a0, uint32_t a1, uint32_t a2, uint32_t a3,
                                         uint32_t b0, uint32_t b1) {
    asm volatile(
        "mma.sync.aligned.m16n8k8.row.col.f32.tf32.tf32.f32 "
        "{%0,%1,%2,%3}, {%4,%5,%6,%7}, {%8,%9}, {%0,%1,%2,%3};"
        : "+f"(d[0]), "+f"(d[1]), "+f"(d[2]), "+f"(d[3])
        : "r"(a0), "r"(a1), "r"(a2), "r"(a3), "r"(b0), "r"(b1));
}

// ldmatrix x4: one instr loads four 8x8-b16 tiles (= four 8x4-f32 tiles)
__device__ __forceinline__ void ldsm4(uint32_t* r, uint32_t addr) {
    asm volatile("ldmatrix.sync.aligned.m8n8.x4.shared.b16 {%0,%1,%2,%3}, [%4];"
        : "=r"(r[0]), "=r"(r[1]), "=r"(r[2]), "=r"(r[3]) : "r"(addr));
}

// ---------------------------------------------------------------------------
// Single fused tf32 rounding pass over x + 4 weights.
// ---------------------------------------------------------------------------
__global__ __launch_bounds__(256) void round_all_kernel(
    const float* __restrict__ x,
    const float* __restrict__ wq, const float* __restrict__ wk,
    const float* __restrict__ wv, const float* __restrict__ wo,
    float* __restrict__ xr,
    float* __restrict__ wqr, float* __restrict__ wkr,
    float* __restrict__ wvr, float* __restrict__ wor)
{
    const int bidx = blockIdx.x;
    const float* src;
    float* dst;
    int off;
    if (bidx < 4096) { src = x; dst = xr; off = bidx; }
    else {
        const int i = (bidx - 4096) >> 10;
        off = (bidx - 4096) & 1023;
        src = (i == 0) ? wq : (i == 1) ? wk : (i == 2) ? wv : wo;
        dst = (i == 0) ? wqr : (i == 1) ? wkr : (i == 2) ? wvr : wor;
    }
    const int idx = off * 256 + threadIdx.x;
    float4 v = ((const float4*)src)[idx];
    float4 o;
    o.x = round_tf32(v.x); o.y = round_tf32(v.y);
    o.z = round_tf32(v.z); o.w = round_tf32(v.w);
    ((float4*)dst)[idx] = o;
}

// ---------------------------------------------------------------------------
// tf32 mma.sync GEMM: tile 256x128, warp 64x64, XOR-swizzled smem,
// ldmatrix fragments. 4 stages (prefetch distance 3), 192KB smem, 1 CTA/SM
// (register-forced anyway: 242 regs x 256 thr).
// ---------------------------------------------------------------------------
#define GTM 256
#define GTN 128
#define A_STAGE_F (GTM * 32)                 // 8192 floats = 32KB
#define B_STAGE_F (GTN * 32)                 // 4096 floats = 16KB
#define STG_F     (A_STAGE_F + B_STAGE_F)    // 12288 floats = 48KB
#define GSTAGES   4
#define GEMM_SMEM (GSTAGES * STG_F * (int)sizeof(float))   // 196608

__global__ __launch_bounds__(256, 1) void gemm_tc_kernel(
    const float* __restrict__ A,
    const float* __restrict__ W0, const float* __restrict__ W1, const float* __restrict__ W2,
    float* __restrict__ C0, float* __restrict__ C1, float* __restrict__ C2,
    int scatter)
{
    const float* __restrict__ W = (blockIdx.z == 0) ? W0 : (blockIdx.z == 1) ? W1 : W2;
    float* __restrict__ C       = (blockIdx.z == 0) ? C0 : (blockIdx.z == 1) ? C1 : C2;

    extern __shared__ float sm[];

    const int tid  = threadIdx.x;
    const int wid  = tid >> 5;
    const int lane = tid & 31;
    const int g    = lane >> 2;          // 0..7 row group
    const int t    = lane & 3;           // 0..3 thread-in-group
    const int wm   = wid & 3;            // warp m index (64 rows each)
    const int wn   = wid >> 2;           // warp n index (64 cols each)
    const int nBase = blockIdx.x * GTN;
    const int mBase = blockIdx.y * GTM;

    float acc[4][8][4];
#pragma unroll
    for (int i = 0; i < 4; i++)
#pragma unroll
        for (int j = 0; j < 8; j++)
#pragma unroll
            for (int l = 0; l < 4; l++) acc[i][j][l] = 0.0f;

    const uint32_t smemA0 = smem_u32(sm);

    const int rowA = wm * 64 + (lane & 15);
    const int rowB = wn * 64 + (lane & 7) + ((lane >> 4) << 3);
    const int c4bitA = lane >> 4;
    const int c4bitB = (lane >> 3) & 1;
    const int lxor   = lane & 7;

    auto issue = [&](int c, int s) {
        const uint32_t st = smemA0 + (uint32_t)(s * STG_F) * 4u;
#pragma unroll
        for (int i = 0; i < 8; i++) {
            const int idx = tid + 256 * i;
            const int r = idx >> 3, c4 = idx & 7;
            const uint32_t off = (uint32_t)(r * 32 + (((c4 ^ (r & 7)) & 7) << 2)) * 4u;
            cp_async16(st + off, A + (size_t)(mBase + r) * DMODEL + c * 32 + c4 * 4);
        }
#pragma unroll
        for (int i = 0; i < 4; i++) {
            const int idx = tid + 256 * i;
            const int r = idx >> 3, c4 = idx & 7;
            const uint32_t off = (uint32_t)(r * 32 + (((c4 ^ (r & 7)) & 7) << 2)) * 4u;
            cp_async16(st + (uint32_t)A_STAGE_F * 4u + off,
                       W + (size_t)(nBase + r) * DMODEL + c * 32 + c4 * 4);
        }
    };

    issue(0, 0); CP_COMMIT();
    issue(1, 1); CP_COMMIT();
    issue(2, 2); CP_COMMIT();

    const int NCHUNK = DMODEL / 32;   // 32
    for (int c = 0; c < NCHUNK; c++) {
        CP_WAIT(2);           // chunk c resident (c+1, c+2 may be in flight)
        __syncthreads();
        if (c + 3 < NCHUNK) issue(c + 3, (c + 3) % GSTAGES);
        CP_COMMIT();          // empty group in tail keeps accounting exact

        const uint32_t Ast = smemA0 + (uint32_t)((c % GSTAGES) * STG_F) * 4u;
        const uint32_t Bst = Ast + (uint32_t)A_STAGE_F * 4u;

#pragma unroll
        for (int ks = 0; ks < 4; ks++) {
            const int xa = ((2 * ks + c4bitA) ^ lxor) & 7;
            const int xb = ((2 * ks + c4bitB) ^ lxor) & 7;

            uint32_t a[4][4];
#pragma unroll
            for (int mt = 0; mt < 4; mt++)
                ldsm4(a[mt], Ast + (uint32_t)((rowA + mt * 16) * 32 + xa * 4) * 4u);

            uint32_t b[4][4];
#pragma unroll
            for (int ntp = 0; ntp < 4; ntp++)
                ldsm4(b[ntp], Bst + (uint32_t)((rowB + ntp * 16) * 32 + xb * 4) * 4u);

#pragma unroll
            for (int mt = 0; mt < 4; mt++)
#pragma unroll
                for (int ntp = 0; ntp < 4; ntp++) {
                    mma_tf32(acc[mt][2 * ntp],     a[mt][0], a[mt][1], a[mt][2], a[mt][3],
                             b[ntp][0], b[ntp][1]);
                    mma_tf32(acc[mt][2 * ntp + 1], a[mt][0], a[mt][1], a[mt][2], a[mt][3],
                             b[ntp][2], b[ntp][3]);
                }
        }
    }

#pragma unroll
    for (int mt = 0; mt < 4; mt++) {
#pragma unroll
        for (int half = 0; half < 2; half++) {
            const int m = mBase + wm * 64 + mt * 16 + g + half * 8;
#pragma unroll
            for (int nt = 0; nt < 8; nt++) {
                const int n = nBase + wn * 64 + nt * 8 + 2 * t;
                float2 v;
                v.x = acc[mt][nt][half * 2 + 0];
                v.y = acc[mt][nt][half * 2 + 1];
                if (scatter) {
                    v.x = round_tf32(v.x); v.y = round_tf32(v.y);
                    const int b = m >> 11, s = m & 2047;
                    const int head = n >> 6, d0 = n & 63;
                    *(float2*)&C[(((size_t)((b << 4) + head) * S_LEN + s) * DK + d0)] = v;
                } else {
                    *(float2*)&C[(size_t)m * DMODEL + n] = v;
                }
            }
        }
    }
}

// ---------------------------------------------------------------------------
// Flash attention with tf32 mma.sync — exact revert to the round-7 (457us)
// scalar-fragment version. CTA: 256 thr (8 warps), Q block 256 rows
// (32 rows = 2 m-tiles per warp), kv tile 64, 2-stage cp.async.
// ---------------------------------------------------------------------------
#define KSTR 68          // sK row stride (floats)
#define VSTR 72          // sV row stride
#define PSTR 68          // sP/sQ row stride
#define SK_F   (64 * KSTR)             // 4352
#define SV_F   (64 * VSTR)             // 4608
#define STAGE_F (SK_F + SV_F)          // 8960
#define SP_OFF (2 * STAGE_F)           // 17920
#define SQ_OFF (SP_OFF + 8 * 32 * PSTR)
#define ATTN_F (SQ_OFF + 8 * 32 * PSTR)
#define ATTN_SMEM (ATTN_F * (int)sizeof(float))   // 210944 bytes

__global__ __launch_bounds__(256) void attn_kernel(
    const float* __restrict__ Q, const float* __restrict__ K,
    const float* __restrict__ V, float* __restrict__ Oatt)
{
    extern __shared__ float sm[];

    const int tid  = threadIdx.x;
    const int wid  = tid >> 5;
    const int lane = tid & 31;
    const int g    = lane >> 2;
    const int t    = lane & 3;
    const int qb   = blockIdx.x;            // 0..7  (256 rows each)
    const int bh   = blockIdx.y;            // 0..31
    const int b    = bh >> 4;
    const int h    = bh & 15;

    float* sPw = sm + SP_OFF + wid * 32 * PSTR;
    float* sQw = sm + SQ_OFF + wid * 32 * PSTR;

    // ---- Stage Q slice (32 rows per warp), pre-scaled by 1/sqrt(dk)=0.125
    {
        const float* Qg = Q + ((size_t)bh * S_LEN + qb * 256 + wid * 32) * DK;
#pragma unroll
        for (int i = 0; i < 16; i++) {
            int idx = lane + 32 * i;
            int r = idx >> 4, c = idx & 15;
            float4 v = *(const float4*)&Qg[r * DK + c * 4];
            v.x *= 0.125f; v.y *= 0.125f; v.z *= 0.125f; v.w *= 0.125f;
            *(float4*)&sQw[r * PSTR + c * 4] = v;
        }
        __syncwarp();
    }

    float o_[2][8][4];
#pragma unroll
    for (int mt = 0; mt < 2; mt++)
#pragma unroll
        for (int nt = 0; nt < 8; nt++)
#pragma unroll
            for (int l = 0; l < 4; l++) o_[mt][nt][l] = 0.0f;
    float mrow[2][2] = {{-1e30f, -1e30f}, {-1e30f, -1e30f}};
    float lrow[2][2] = {{0.0f, 0.0f}, {0.0f, 0.0f}};

    const float* Kg = K + (size_t)bh * S_LEN * DK;
    const float* Vg = V + (size_t)bh * S_LEN * DK;
    const uint32_t smemB = smem_u32(sm);

    auto issue = [&](int kv, int st) {
        uint32_t dK = smemB + (uint32_t)(st * STAGE_F) * 4u;
        uint32_t dV = dK + (uint32_t)SK_F * 4u;
        const float* kS = Kg + (size_t)kv * 64 * DK;
        const float* vS = Vg + (size_t)kv * 64 * DK;
#pragma unroll
        for (int i = 0; i < 4; i++) {
            int q4 = tid + 256 * i;
            int r = q4 >> 4, qc = q4 & 15;
            cp_async16(dK + (uint32_t)(r * KSTR + qc * 4) * 4u, kS + r * DK + qc * 4);
            cp_async16(dV + (uint32_t)(r * VSTR + qc * 4) * 4u, vS + r * DK + qc * 4);
        }
    };

    issue(0, 0); CP_COMMIT();

    const int NKV = S_LEN / 64;   // 32
    for (int kv = 0; kv < NKV; kv++) {
        CP_WAIT(0);
        __syncthreads();
        if (kv + 1 < NKV) issue(kv + 1, (kv + 1) & 1);
        CP_COMMIT();

        const float* sK = sm + (kv & 1) * STAGE_F;
        const float* sV = sK + SK_F;

        // ---- scores S = (Q/8) K^T   (32 x 64 per warp; K frags reused x2)
        float s_[2][8][4];
#pragma unroll
        for (int mt = 0; mt < 2; mt++)
#pragma unroll
            for (int nt = 0; nt < 8; nt++)
#pragma unroll
                for (int l = 0; l < 4; l++) s_[mt][nt][l] = 0.0f;

#pragma unroll
        for (int ks = 0; ks < 8; ks++) {
            uint32_t a[2][4];
#pragma unroll
            for (int mt = 0; mt < 2; mt++) {
                const float* Ar = sQw + (mt * 16 + g) * PSTR + ks * 8;
                a[mt][0] = __float_as_uint(Ar[t]);
                a[mt][1] = __float_as_uint(Ar[8 * PSTR + t]);
                a[mt][2] = __float_as_uint(Ar[t + 4]);
                a[mt][3] = __float_as_uint(Ar[8 * PSTR + t + 4]);
            }
#pragma unroll
            for (int nt = 0; nt < 8; nt++) {
                const float* Kr = sK + (nt * 8 + g) * KSTR + ks * 8;
                uint32_t b0 = __float_as_uint(Kr[t]);
                uint32_t b1 = __float_as_uint(Kr[t + 4]);
                mma_tf32(s_[0][nt], a[0][0], a[0][1], a[0][2], a[0][3], b0, b1);
                mma_tf32(s_[1][nt], a[1][0], a[1][1], a[1][2], a[1][3], b0, b1);
            }
        }

        // ---- online softmax per m-tile
#pragma unroll
        for (int mt = 0; mt < 2; mt++) {
            float mx0 = -1e30f, mx1 = -1e30f;
#pragma unroll
            for (int nt = 0; nt < 8; nt++) {
                mx0 = fmaxf(mx0, fmaxf(s_[mt][nt][0], s_[mt][nt][1]));
                mx1 = fmaxf(mx1, fmaxf(s_[mt][nt][2], s_[mt][nt][3]));
            }
            mx0 = fmaxf(mx0, __shfl_xor_sync(0xffffffffu, mx0, 1));
            mx0 = fmaxf(mx0, __shfl_xor_sync(0xffffffffu, mx0, 2));
            mx1 = fmaxf(mx1, __shfl_xor_sync(0xffffffffu, mx1, 1));
            mx1 = fmaxf(mx1, __shfl_xor_sync(0xffffffffu, mx1, 2));

            float mn0 = fmaxf(mrow[mt][0], mx0), mn1 = fmaxf(mrow[mt][1], mx1);
            float al0 = __expf(mrow[mt][0] - mn0), al1 = __expf(mrow[mt][1] - mn1);
            mrow[mt][0] = mn0; mrow[mt][1] = mn1;

            float s0 = 0.0f, s1 = 0.0f;
#pragma unroll
            for (int nt = 0; nt < 8; nt++) {
                s_[mt][nt][0] = __expf(s_[mt][nt][0] - mn0); s0 += s_[mt][nt][0];
                s_[mt][nt][1] = __expf(s_[mt][nt][1] - mn0); s0 += s_[mt][nt][1];
                s_[mt][nt][2] = __expf(s_[mt][nt][2] - mn1); s1 += s_[mt][nt][2];
                s_[mt][nt][3] = __expf(s_[mt][nt][3] - mn1); s1 += s_[mt][nt][3];
            }
            s0 += __shfl_xor_sync(0xffffffffu, s0, 1);
            s0 += __shfl_xor_sync(0xffffffffu, s0, 2);
            s1 += __shfl_xor_sync(0xffffffffu, s1, 1);
            s1 += __shfl_xor_sync(0xffffffffu, s1, 2);
            lrow[mt][0] = lrow[mt][0] * al0 + s0;
            lrow[mt][1] = lrow[mt][1] * al1 + s1;

#pragma unroll
            for (int nt = 0; nt < 8; nt++) {
                o_[mt][nt][0] *= al0; o_[mt][nt][1] *= al0;
                o_[mt][nt][2] *= al1; o_[mt][nt][3] *= al1;
            }

            // stage P (tf32-rounded) D-layout -> A-layout
#pragma unroll
            for (int nt = 0; nt < 8; nt++) {
                float2 p01 = make_float2(round_tf32(s_[mt][nt][0]), round_tf32(s_[mt][nt][1]));
                float2 p23 = make_float2(round_tf32(s_[mt][nt][2]), round_tf32(s_[mt][nt][3]));
                *(float2*)&sPw[(mt * 16 + g) * PSTR + nt * 8 + 2 * t]     = p01;
                *(float2*)&sPw[(mt * 16 + g + 8) * PSTR + nt * 8 + 2 * t] = p23;
            }
        }
        __syncwarp();

        // ---- O += P V   (32 x 64 per warp; V frags reused x2)
#pragma unroll
        for (int kt = 0; kt < 8; kt++) {
            uint32_t a[2][4];
#pragma unroll
            for (int mt = 0; mt < 2; mt++) {
                const float* Pr = sPw + (mt * 16 + g) * PSTR + kt * 8;
                a[mt][0] = __float_as_uint(Pr[t]);
                a[mt][1] = __float_as_uint(Pr[8 * PSTR + t]);
                a[mt][2] = __float_as_uint(Pr[t + 4]);
                a[mt][3] = __float_as_uint(Pr[8 * PSTR + t + 4]);
            }
#pragma unroll
            for (int nt = 0; nt < 8; nt++) {
                const float* Vr = sV + (kt * 8 + t) * VSTR + nt * 8 + g;
                uint32_t b0 = __float_as_uint(Vr[0]);
                uint32_t b1 = __float_as_uint(Vr[4 * VSTR]);
                mma_tf32(o_[0][nt], a[0][0], a[0][1], a[0][2], a[0][3], b0, b1);
                mma_tf32(o_[1][nt], a[1][0], a[1][1], a[1][2], a[1][3], b0, b1);
            }
        }
        __syncwarp();
    }

    // ---- epilogue: normalize, round to tf32, write (B,S,D)
#pragma unroll
    for (int mt = 0; mt < 2; mt++) {
        const float inv0 = 1.0f / lrow[mt][0], inv1 = 1.0f / lrow[mt][1];
        const int row0 = qb * 256 + wid * 32 + mt * 16 + g;
#pragma unroll
        for (int nt = 0; nt < 8; nt++) {
            const int col = h * DK + nt * 8 + 2 * t;
            float2 v0, v1;
            v0.x = round_tf32(o_[mt][nt][0] * inv0); v0.y = round_tf32(o_[mt][nt][1] * inv0);
            v1.x = round_tf32(o_[mt][nt][2] * inv1); v1.y = round_tf32(o_[mt][nt][3] * inv1);
            *(float2*)&Oatt[((size_t)b * S_LEN + row0) * DMODEL + col]     = v0;
            *(float2*)&Oatt[((size_t)b * S_LEN + row0 + 8) * DMODEL + col] = v1;
        }
    }
}

// ---------------------------------------------------------------------------
extern "C" void kernel_launch(void* const* d_in, const int* in_sizes, int n_in,
                              void* d_out, int out_size)
{
    const float* x  = (const float*)d_in[0];
    const float* Wq = (const float*)d_in[1];
    const float* Wk = (const float*)d_in[2];
    const float* Wv = (const float*)d_in[3];
    const float* Wo = (const float*)d_in[4];
    float* out = (float*)d_out;

    float *qp, *kp, *vp, *attp, *rp;
    cudaGetSymbolAddress((void**)&qp,   g_q);
    cudaGetSymbolAddress((void**)&kp,   g_k);
    cudaGetSymbolAddress((void**)&vp,   g_v);
    cudaGetSymbolAddress((void**)&attp, g_att);
    cudaGetSymbolAddress((void**)&rp,   g_round);

    float* xr  = rp;
    float* wqr = rp + 4 * 1024 * 1024;
    float* wkr = rp + 5 * 1024 * 1024;
    float* wvr = rp + 6 * 1024 * 1024;
    float* wor = rp + 7 * 1024 * 1024;

    // 0) single fused tf32 rna pre-rounding of all GEMM inputs
    round_all_kernel<<<8192, 256>>>(x, Wq, Wk, Wv, Wo, xr, wqr, wkr, wvr, wor);

    cudaFuncSetAttribute(gemm_tc_kernel, cudaFuncAttributeMaxDynamicSharedMemorySize,
                         GEMM_SMEM);
    cudaFuncSetAttribute(attn_kernel, cudaFuncAttributeMaxDynamicSharedMemorySize,
                         ATTN_SMEM);

    // 1) Fused QKV projections (tf32 mma), scatter+round to (B,H,S,dk)
    dim3 gQKV(DMODEL / GTN, M_TOTAL / GTM, 3);
    gemm_tc_kernel<<<gQKV, 256, GEMM_SMEM>>>(xr, wqr, wkr, wvr, qp, kp, vp, 1);

    // 2) Flash attention (tf32 mma) -> (B,S,D), rounded
    dim3 gA(S_LEN / 256, BATCH * NHEADS);
    attn_kernel<<<gA, 256, ATTN_SMEM>>>(qp, kp, vp, attp);

    // 3) Output projection (tf32 mma) -> d_out
    dim3 gO(DMODEL / GTN, M_TOTAL / GTM, 1);
    gemm_tc_kernel<<<gO, 256, GEMM_SMEM>>>(attp, wor, wor, wor, out, out, out, 0);
}

// round 12
// speedup vs baseline: 1.0787x; 1.0183x over previous
#include <cuda_runtime.h>
#include <cstdint>

// Problem constants
#define S_LEN    2048
#define DMODEL   1024
#define NHEADS   16
#define DK       64
#define BATCH    2
#define M_TOTAL  (BATCH * S_LEN)   // 4096

// Scratch (allocation-free rule: __device__ globals)
__device__ float g_q[BATCH * NHEADS * S_LEN * DK];     // (B,H,S,dk) tf32-rounded
__device__ float g_k[BATCH * NHEADS * S_LEN * DK];
__device__ float g_v[BATCH * NHEADS * S_LEN * DK];
__device__ float g_att[BATCH * S_LEN * DMODEL];        // (B,S,D) tf32-rounded
__device__ float g_round[8 * 1024 * 1024];             // rounded x + 4 weights

// ---------------------------------------------------------------------------
// Helpers
// ---------------------------------------------------------------------------
__device__ __forceinline__ uint32_t smem_u32(const void* p) {
    uint32_t a;
    asm("{ .reg .u64 t; cvta.to.shared.u64 t, %1; cvt.u32.u64 %0, t; }"
        : "=r"(a) : "l"(p));
    return a;
}

__device__ __forceinline__ void cp_async16(uint32_t s, const void* g) {
    asm volatile("cp.async.cg.shared.global [%0], [%1], 16;" :: "r"(s), "l"(g));
}
#define CP_COMMIT() asm volatile("cp.async.commit_group;" ::: "memory")
#define CP_WAIT(n)  asm volatile("cp.async.wait_group %0;" :: "n"(n) : "memory")

__device__ __forceinline__ float round_tf32(float v) {
    uint32_t u;
    asm("cvt.rna.tf32.f32 %0, %1;" : "=r"(u) : "f"(v));
    return __uint_as_float(u);
}

// D(16x8) += A(16x8,row) * B(8x8,col)  -- tf32, fp32 accum
__device__ __forceinline__ void mma_tf32(float* d,
                                         uint32_t a0, uint32_t a1, uint32_t a2, uint32_t a3,
                                         uint32_t b0, uint32_t b1) {
    asm volatile(
        "mma.sync.aligned.m16n8k8.row.col.f32.tf32.tf32.f32 "
        "{%0,%1,%2,%3}, {%4,%5,%6,%7}, {%8,%9}, {%0,%1,%2,%3};"
        : "+f"(d[0]), "+f"(d[1]), "+f"(d[2]), "+f"(d[3])
        : "r"(a0), "r"(a1), "r"(a2), "r"(a3), "r"(b0), "r"(b1));
}

// ldmatrix x4: one instr loads four 8x8-b16 tiles (= four 8x4-f32 tiles)
__device__ __forceinline__ void ldsm4(uint32_t* r, uint32_t addr) {
    asm volatile("ldmatrix.sync.aligned.m8n8.x4.shared.b16 {%0,%1,%2,%3}, [%4];"
        : "=r"(r[0]), "=r"(r[1]), "=r"(r[2]), "=r"(r[3]) : "r"(addr));
}

// ---------------------------------------------------------------------------
// Single fused tf32 rounding pass over x + 4 weights. 4 float4 per thread.
// Blocks [0,1024) -> x (1M float4); [1024+256*i, ...) -> weight i (256K float4).
// ---------------------------------------------------------------------------
__global__ __launch_bounds__(256) void round_all_kernel(
    const float* __restrict__ x,
    const float* __restrict__ wq, const float* __restrict__ wk,
    const float* __restrict__ wv, const float* __restrict__ wo,
    float* __restrict__ xr,
    float* __restrict__ wqr, float* __restrict__ wkr,
    float* __restrict__ wvr, float* __restrict__ wor)
{
    const int bidx = blockIdx.x;
    const float* src;
    float* dst;
    int off;
    if (bidx < 1024) { src = x; dst = xr; off = bidx; }
    else {
        const int i = (bidx - 1024) >> 8;
        off = (bidx - 1024) & 255;
        src = (i == 0) ? wq : (i == 1) ? wk : (i == 2) ? wv : wo;
        dst = (i == 0) ? wqr : (i == 1) ? wkr : (i == 2) ? wvr : wor;
    }
    const int base = off * 1024 + threadIdx.x;
#pragma unroll
    for (int j = 0; j < 4; j++) {
        float4 v = ((const float4*)src)[base + j * 256];
        float4 o;
        o.x = round_tf32(v.x); o.y = round_tf32(v.y);
        o.z = round_tf32(v.z); o.w = round_tf32(v.w);
        ((float4*)dst)[base + j * 256] = o;
    }
}

// ---------------------------------------------------------------------------
// tf32 mma.sync GEMM: tile 256x128, warp 64x64, XOR-swizzled panel smem,
// ldmatrix fragments. K-chunk 64 (two 32-float panels), 2 stages (96KB each),
// distance-1 prefetch (compute ~3x load). Syncs halved vs 32-chunk version.
// Accumulation order identical to prior rounds (bit-exact).
// ---------------------------------------------------------------------------
#define GTM 256
#define GTN 128
#define CHUNK_K   64
#define A_PANEL_F (GTM * 32)                 // 8192 floats
#define B_PANEL_F (GTN * 32)                 // 4096 floats
#define A_STAGE_F (2 * A_PANEL_F)            // 16384 floats = 64KB
#define B_STAGE_F (2 * B_PANEL_F)            // 8192 floats = 32KB
#define STG_F     (A_STAGE_F + B_STAGE_F)    // 24576 floats = 96KB
#define GSTAGES   2
#define GEMM_SMEM (GSTAGES * STG_F * (int)sizeof(float))   // 196608

__global__ __launch_bounds__(256, 1) void gemm_tc_kernel(
    const float* __restrict__ A,
    const float* __restrict__ W0, const float* __restrict__ W1, const float* __restrict__ W2,
    float* __restrict__ C0, float* __restrict__ C1, float* __restrict__ C2,
    int scatter)
{
    const float* __restrict__ W = (blockIdx.z == 0) ? W0 : (blockIdx.z == 1) ? W1 : W2;
    float* __restrict__ C       = (blockIdx.z == 0) ? C0 : (blockIdx.z == 1) ? C1 : C2;

    extern __shared__ float sm[];

    const int tid  = threadIdx.x;
    const int wid  = tid >> 5;
    const int lane = tid & 31;
    const int g    = lane >> 2;          // 0..7 row group
    const int t    = lane & 3;           // 0..3 thread-in-group
    const int wm   = wid & 3;            // warp m index (64 rows each)
    const int wn   = wid >> 2;           // warp n index (64 cols each)
    const int nBase = blockIdx.x * GTN;
    const int mBase = blockIdx.y * GTM;

    float acc[4][8][4];
#pragma unroll
    for (int i = 0; i < 4; i++)
#pragma unroll
        for (int j = 0; j < 8; j++)
#pragma unroll
            for (int l = 0; l < 4; l++) acc[i][j][l] = 0.0f;

    const uint32_t smemA0 = smem_u32(sm);

    const int rowA = wm * 64 + (lane & 15);
    const int rowB = wn * 64 + (lane & 7) + ((lane >> 4) << 3);
    const int c4bitA = lane >> 4;
    const int c4bitB = (lane >> 3) & 1;
    const int lxor   = lane & 7;

    // issue loads for 64-K chunk c into stage s (two swizzled 32-col panels)
    auto issue = [&](int c, int s) {
        const uint32_t st = smemA0 + (uint32_t)(s * STG_F) * 4u;
        // A: 256 rows x 16 col-groups = 4096 x 16B, 16 per thread
#pragma unroll
        for (int i = 0; i < 16; i++) {
            const int idx = tid + 256 * i;
            const int r = idx >> 4, cg = idx & 15;
            const int pan = cg >> 3, c4 = cg & 7;
            const uint32_t off =
                (uint32_t)(pan * A_PANEL_F + r * 32 + (((c4 ^ (r & 7)) & 7) << 2)) * 4u;
            cp_async16(st + off, A + (size_t)(mBase + r) * DMODEL + c * CHUNK_K + cg * 4);
        }
        // B: 128 rows x 16 col-groups = 2048 x 16B, 8 per thread
#pragma unroll
        for (int i = 0; i < 8; i++) {
            const int idx = tid + 256 * i;
            const int r = idx >> 4, cg = idx & 15;
            const int pan = cg >> 3, c4 = cg & 7;
            const uint32_t off =
                (uint32_t)(pan * B_PANEL_F + r * 32 + (((c4 ^ (r & 7)) & 7) << 2)) * 4u;
            cp_async16(st + (uint32_t)A_STAGE_F * 4u + off,
                       W + (size_t)(nBase + r) * DMODEL + c * CHUNK_K + cg * 4);
        }
    };

    issue(0, 0); CP_COMMIT();

    const int NCHUNK = DMODEL / CHUNK_K;   // 16
    for (int c = 0; c < NCHUNK; c++) {
        CP_WAIT(0);           // chunk c resident
        __syncthreads();
        if (c + 1 < NCHUNK) issue(c + 1, (c + 1) & 1);
        CP_COMMIT();          // empty group in tail keeps accounting exact

        const uint32_t Ast = smemA0 + (uint32_t)((c & 1) * STG_F) * 4u;
        const uint32_t Bst = Ast + (uint32_t)A_STAGE_F * 4u;

#pragma unroll
        for (int ks = 0; ks < 8; ks++) {
            const uint32_t panA = (uint32_t)((ks >> 2) * A_PANEL_F) * 4u;
            const uint32_t panB = (uint32_t)((ks >> 2) * B_PANEL_F) * 4u;
            const int k2 = ks & 3;
            const int xa = ((2 * k2 + c4bitA) ^ lxor) & 7;
            const int xb = ((2 * k2 + c4bitB) ^ lxor) & 7;

            uint32_t a[4][4];
#pragma unroll
            for (int mt = 0; mt < 4; mt++)
                ldsm4(a[mt], Ast + panA + (uint32_t)((rowA + mt * 16) * 32 + xa * 4) * 4u);

            uint32_t b[4][4];
#pragma unroll
            for (int ntp = 0; ntp < 4; ntp++)
                ldsm4(b[ntp], Bst + panB + (uint32_t)((rowB + ntp * 16) * 32 + xb * 4) * 4u);

#pragma unroll
            for (int mt = 0; mt < 4; mt++)
#pragma unroll
                for (int ntp = 0; ntp < 4; ntp++) {
                    mma_tf32(acc[mt][2 * ntp],     a[mt][0], a[mt][1], a[mt][2], a[mt][3],
                             b[ntp][0], b[ntp][1]);
                    mma_tf32(acc[mt][2 * ntp + 1], a[mt][0], a[mt][1], a[mt][2], a[mt][3],
                             b[ntp][2], b[ntp][3]);
                }
        }
    }

#pragma unroll
    for (int mt = 0; mt < 4; mt++) {
#pragma unroll
        for (int half = 0; half < 2; half++) {
            const int m = mBase + wm * 64 + mt * 16 + g + half * 8;
#pragma unroll
            for (int nt = 0; nt < 8; nt++) {
                const int n = nBase + wn * 64 + nt * 8 + 2 * t;
                float2 v;
                v.x = acc[mt][nt][half * 2 + 0];
                v.y = acc[mt][nt][half * 2 + 1];
                if (scatter) {
                    v.x = round_tf32(v.x); v.y = round_tf32(v.y);
                    const int b = m >> 11, s = m & 2047;
                    const int head = n >> 6, d0 = n & 63;
                    *(float2*)&C[(((size_t)((b << 4) + head) * S_LEN + s) * DK + d0)] = v;
                } else {
                    *(float2*)&C[(size_t)m * DMODEL + n] = v;
                }
            }
        }
    }
}

// ---------------------------------------------------------------------------
// Flash attention with tf32 mma.sync — unchanged 455us version (scalar frags).
// CTA: 256 thr (8 warps), Q block 256 rows (32/warp), kv tile 64, 2 stages.
// ---------------------------------------------------------------------------
#define KSTR 68          // sK row stride (floats)
#define VSTR 72          // sV row stride
#define PSTR 68          // sP/sQ row stride
#define SK_F   (64 * KSTR)             // 4352
#define SV_F   (64 * VSTR)             // 4608
#define STAGE_F (SK_F + SV_F)          // 8960
#define SP_OFF (2 * STAGE_F)           // 17920
#define SQ_OFF (SP_OFF + 8 * 32 * PSTR)
#define ATTN_F (SQ_OFF + 8 * 32 * PSTR)
#define ATTN_SMEM (ATTN_F * (int)sizeof(float))   // 210944 bytes

__global__ __launch_bounds__(256) void attn_kernel(
    const float* __restrict__ Q, const float* __restrict__ K,
    const float* __restrict__ V, float* __restrict__ Oatt)
{
    extern __shared__ float sm[];

    const int tid  = threadIdx.x;
    const int wid  = tid >> 5;
    const int lane = tid & 31;
    const int g    = lane >> 2;
    const int t    = lane & 3;
    const int qb   = blockIdx.x;            // 0..7  (256 rows each)
    const int bh   = blockIdx.y;            // 0..31
    const int b    = bh >> 4;
    const int h    = bh & 15;

    float* sPw = sm + SP_OFF + wid * 32 * PSTR;
    float* sQw = sm + SQ_OFF + wid * 32 * PSTR;

    // ---- Stage Q slice (32 rows per warp), pre-scaled by 1/sqrt(dk)=0.125
    {
        const float* Qg = Q + ((size_t)bh * S_LEN + qb * 256 + wid * 32) * DK;
#pragma unroll
        for (int i = 0; i < 16; i++) {
            int idx = lane + 32 * i;
            int r = idx >> 4, c = idx & 15;
            float4 v = *(const float4*)&Qg[r * DK + c * 4];
            v.x *= 0.125f; v.y *= 0.125f; v.z *= 0.125f; v.w *= 0.125f;
            *(float4*)&sQw[r * PSTR + c * 4] = v;
        }
        __syncwarp();
    }

    float o_[2][8][4];
#pragma unroll
    for (int mt = 0; mt < 2; mt++)
#pragma unroll
        for (int nt = 0; nt < 8; nt++)
#pragma unroll
            for (int l = 0; l < 4; l++) o_[mt][nt][l] = 0.0f;
    float mrow[2][2] = {{-1e30f, -1e30f}, {-1e30f, -1e30f}};
    float lrow[2][2] = {{0.0f, 0.0f}, {0.0f, 0.0f}};

    const float* Kg = K + (size_t)bh * S_LEN * DK;
    const float* Vg = V + (size_t)bh * S_LEN * DK;
    const uint32_t smemB = smem_u32(sm);

    auto issue = [&](int kv, int st) {
        uint32_t dK = smemB + (uint32_t)(st * STAGE_F) * 4u;
        uint32_t dV = dK + (uint32_t)SK_F * 4u;
        const float* kS = Kg + (size_t)kv * 64 * DK;
        const float* vS = Vg + (size_t)kv * 64 * DK;
#pragma unroll
        for (int i = 0; i < 4; i++) {
            int q4 = tid + 256 * i;
            int r = q4 >> 4, qc = q4 & 15;
            cp_async16(dK + (uint32_t)(r * KSTR + qc * 4) * 4u, kS + r * DK + qc * 4);
            cp_async16(dV + (uint32_t)(r * VSTR + qc * 4) * 4u, vS + r * DK + qc * 4);
        }
    };

    issue(0, 0); CP_COMMIT();

    const int NKV = S_LEN / 64;   // 32
    for (int kv = 0; kv < NKV; kv++) {
        CP_WAIT(0);
        __syncthreads();
        if (kv + 1 < NKV) issue(kv + 1, (kv + 1) & 1);
        CP_COMMIT();

        const float* sK = sm + (kv & 1) * STAGE_F;
        const float* sV = sK + SK_F;

        // ---- scores S = (Q/8) K^T   (32 x 64 per warp; K frags reused x2)
        float s_[2][8][4];
#pragma unroll
        for (int mt = 0; mt < 2; mt++)
#pragma unroll
            for (int nt = 0; nt < 8; nt++)
#pragma unroll
                for (int l = 0; l < 4; l++) s_[mt][nt][l] = 0.0f;

#pragma unroll
        for (int ks = 0; ks < 8; ks++) {
            uint32_t a[2][4];
#pragma unroll
            for (int mt = 0; mt < 2; mt++) {
                const float* Ar = sQw + (mt * 16 + g) * PSTR + ks * 8;
                a[mt][0] = __float_as_uint(Ar[t]);
                a[mt][1] = __float_as_uint(Ar[8 * PSTR + t]);
                a[mt][2] = __float_as_uint(Ar[t + 4]);
                a[mt][3] = __float_as_uint(Ar[8 * PSTR + t + 4]);
            }
#pragma unroll
            for (int nt = 0; nt < 8; nt++) {
                const float* Kr = sK + (nt * 8 + g) * KSTR + ks * 8;
                uint32_t b0 = __float_as_uint(Kr[t]);
                uint32_t b1 = __float_as_uint(Kr[t + 4]);
                mma_tf32(s_[0][nt], a[0][0], a[0][1], a[0][2], a[0][3], b0, b1);
                mma_tf32(s_[1][nt], a[1][0], a[1][1], a[1][2], a[1][3], b0, b1);
            }
        }

        // ---- online softmax per m-tile
#pragma unroll
        for (int mt = 0; mt < 2; mt++) {
            float mx0 = -1e30f, mx1 = -1e30f;
#pragma unroll
            for (int nt = 0; nt < 8; nt++) {
                mx0 = fmaxf(mx0, fmaxf(s_[mt][nt][0], s_[mt][nt][1]));
                mx1 = fmaxf(mx1, fmaxf(s_[mt][nt][2], s_[mt][nt][3]));
            }
            mx0 = fmaxf(mx0, __shfl_xor_sync(0xffffffffu, mx0, 1));
            mx0 = fmaxf(mx0, __shfl_xor_sync(0xffffffffu, mx0, 2));
            mx1 = fmaxf(mx1, __shfl_xor_sync(0xffffffffu, mx1, 1));
            mx1 = fmaxf(mx1, __shfl_xor_sync(0xffffffffu, mx1, 2));

            float mn0 = fmaxf(mrow[mt][0], mx0), mn1 = fmaxf(mrow[mt][1], mx1);
            float al0 = __expf(mrow[mt][0] - mn0), al1 = __expf(mrow[mt][1] - mn1);
            mrow[mt][0] = mn0; mrow[mt][1] = mn1;

            float s0 = 0.0f, s1 = 0.0f;
#pragma unroll
            for (int nt = 0; nt < 8; nt++) {
                s_[mt][nt][0] = __expf(s_[mt][nt][0] - mn0); s0 += s_[mt][nt][0];
                s_[mt][nt][1] = __expf(s_[mt][nt][1] - mn0); s0 += s_[mt][nt][1];
                s_[mt][nt][2] = __expf(s_[mt][nt][2] - mn1); s1 += s_[mt][nt][2];
                s_[mt][nt][3] = __expf(s_[mt][nt][3] - mn1); s1 += s_[mt][nt][3];
            }
            s0 += __shfl_xor_sync(0xffffffffu, s0, 1);
            s0 += __shfl_xor_sync(0xffffffffu, s0, 2);
            s1 += __shfl_xor_sync(0xffffffffu, s1, 1);
            s1 += __shfl_xor_sync(0xffffffffu, s1, 2);
            lrow[mt][0] = lrow[mt][0] * al0 + s0;
            lrow[mt][1] = lrow[mt][1] * al1 + s1;

#pragma unroll
            for (int nt = 0; nt < 8; nt++) {
                o_[mt][nt][0] *= al0; o_[mt][nt][1] *= al0;
                o_[mt][nt][2] *= al1; o_[mt][nt][3] *= al1;
            }

            // stage P (tf32-rounded) D-layout -> A-layout
#pragma unroll
            for (int nt = 0; nt < 8; nt++) {
                float2 p01 = make_float2(round_tf32(s_[mt][nt][0]), round_tf32(s_[mt][nt][1]));
                float2 p23 = make_float2(round_tf32(s_[mt][nt][2]), round_tf32(s_[mt][nt][3]));
                *(float2*)&sPw[(mt * 16 + g) * PSTR + nt * 8 + 2 * t]     = p01;
                *(float2*)&sPw[(mt * 16 + g + 8) * PSTR + nt * 8 + 2 * t] = p23;
            }
        }
        __syncwarp();

        // ---- O += P V   (32 x 64 per warp; V frags reused x2)
#pragma unroll
        for (int kt = 0; kt < 8; kt++) {
            uint32_t a[2][4];
#pragma unroll
            for (int mt = 0; mt < 2; mt++) {
                const float* Pr = sPw + (mt * 16 + g) * PSTR + kt * 8;
                a[mt][0] = __float_as_uint(Pr[t]);
                a[mt][1] = __float_as_uint(Pr[8 * PSTR + t]);
                a[mt][2] = __float_as_uint(Pr[t + 4]);
                a[mt][3] = __float_as_uint(Pr[8 * PSTR + t + 4]);
            }
#pragma unroll
            for (int nt = 0; nt < 8; nt++) {
                const float* Vr = sV + (kt * 8 + t) * VSTR + nt * 8 + g;
                uint32_t b0 = __float_as_uint(Vr[0]);
                uint32_t b1 = __float_as_uint(Vr[4 * VSTR]);
                mma_tf32(o_[0][nt], a[0][0], a[0][1], a[0][2], a[0][3], b0, b1);
                mma_tf32(o_[1][nt], a[1][0], a[1][1], a[1][2], a[1][3], b0, b1);
            }
        }
        __syncwarp();
    }

    // ---- epilogue: normalize, round to tf32, write (B,S,D)
#pragma unroll
    for (int mt = 0; mt < 2; mt++) {
        const float inv0 = 1.0f / lrow[mt][0], inv1 = 1.0f / lrow[mt][1];
        const int row0 = qb * 256 + wid * 32 + mt * 16 + g;
#pragma unroll
        for (int nt = 0; nt < 8; nt++) {
            const int col = h * DK + nt * 8 + 2 * t;
            float2 v0, v1;
            v0.x = round_tf32(o_[mt][nt][0] * inv0); v0.y = round_tf32(o_[mt][nt][1] * inv0);
            v1.x = round_tf32(o_[mt][nt][2] * inv1); v1.y = round_tf32(o_[mt][nt][3] * inv1);
            *(float2*)&Oatt[((size_t)b * S_LEN + row0) * DMODEL + col]     = v0;
            *(float2*)&Oatt[((size_t)b * S_LEN + row0 + 8) * DMODEL + col] = v1;
        }
    }
}

// ---------------------------------------------------------------------------
extern "C" void kernel_launch(void* const* d_in, const int* in_sizes, int n_in,
                              void* d_out, int out_size)
{
    const float* x  = (const float*)d_in[0];
    const float* Wq = (const float*)d_in[1];
    const float* Wk = (const float*)d_in[2];
    const float* Wv = (const float*)d_in[3];
    const float* Wo = (const float*)d_in[4];
    float* out = (float*)d_out;

    float *qp, *kp, *vp, *attp, *rp;
    cudaGetSymbolAddress((void**)&qp,   g_q);
    cudaGetSymbolAddress((void**)&kp,   g_k);
    cudaGetSymbolAddress((void**)&vp,   g_v);
    cudaGetSymbolAddress((void**)&attp, g_att);
    cudaGetSymbolAddress((void**)&rp,   g_round);

    float* xr  = rp;
    float* wqr = rp + 4 * 1024 * 1024;
    float* wkr = rp + 5 * 1024 * 1024;
    float* wvr = rp + 6 * 1024 * 1024;
    float* wor = rp + 7 * 1024 * 1024;

    // 0) single fused tf32 rna pre-rounding of all GEMM inputs
    round_all_kernel<<<2048, 256>>>(x, Wq, Wk, Wv, Wo, xr, wqr, wkr, wvr, wor);

    cudaFuncSetAttribute(gemm_tc_kernel, cudaFuncAttributeMaxDynamicSharedMemorySize,
                         GEMM_SMEM);
    cudaFuncSetAttribute(attn_kernel, cudaFuncAttributeMaxDynamicSharedMemorySize,
                         ATTN_SMEM);

    // 1) Fused QKV projections (tf32 mma), scatter+round to (B,H,S,dk)
    dim3 gQKV(DMODEL / GTN, M_TOTAL / GTM, 3);
    gemm_tc_kernel<<<gQKV, 256, GEMM_SMEM>>>(xr, wqr, wkr, wvr, qp, kp, vp, 1);

    // 2) Flash attention (tf32 mma) -> (B,S,D), rounded
    dim3 gA(S_LEN / 256, BATCH * NHEADS);
    attn_kernel<<<gA, 256, ATTN_SMEM>>>(qp, kp, vp, attp);

    // 3) Output projection (tf32 mma) -> d_out
    dim3 gO(DMODEL / GTN, M_TOTAL / GTM, 1);
    gemm_tc_kernel<<<gO, 256, GEMM_SMEM>>>(attp, wor, wor, wor, out, out, out, 0);
}

// round 14
// speedup vs baseline: 1.9297x; 1.7889x over previous
#include <cuda_runtime.h>
#include <cuda_fp16.h>
#include <cstdint>

// Problem constants
#define S_LEN    2048
#define DMODEL   1024
#define NHEADS   16
#define DK       64
#define BATCH    2
#define M_TOTAL  (BATCH * S_LEN)   // 4096

// Scratch (allocation-free rule: __device__ globals)
__device__ __half g_q[BATCH * NHEADS * S_LEN * DK];    // (B,H,S,dk) fp16
__device__ __half g_k[BATCH * NHEADS * S_LEN * DK];
__device__ __half g_v[BATCH * NHEADS * S_LEN * DK];
__device__ __half g_att[BATCH * S_LEN * DMODEL];       // (B,S,D) fp16
__device__ __half g_half[8 * 1024 * 1024];             // fp16 x + 4 weights

// ---------------------------------------------------------------------------
// Helpers
// ---------------------------------------------------------------------------
__device__ __forceinline__ uint32_t smem_u32(const void* p) {
    uint32_t a;
    asm("{ .reg .u64 t; cvta.to.shared.u64 t, %1; cvt.u32.u64 %0, t; }"
        : "=r"(a) : "l"(p));
    return a;
}

__device__ __forceinline__ void cp_async16(uint32_t s, const void* g) {
    asm volatile("cp.async.cg.shared.global [%0], [%1], 16;" :: "r"(s), "l"(g));
}
#define CP_COMMIT() asm volatile("cp.async.commit_group;" ::: "memory")
#define CP_WAIT(n)  asm volatile("cp.async.wait_group %0;" :: "n"(n) : "memory")

// D(16x8) += A(16x16,row) * B(16x8,col) -- fp16 operands, fp32 accum
__device__ __forceinline__ void mma_f16(float* d,
                                        uint32_t a0, uint32_t a1, uint32_t a2, uint32_t a3,
                                        uint32_t b0, uint32_t b1) {
    asm volatile(
        "mma.sync.aligned.m16n8k16.row.col.f32.f16.f16.f32 "
        "{%0,%1,%2,%3}, {%4,%5,%6,%7}, {%8,%9}, {%0,%1,%2,%3};"
        : "+f"(d[0]), "+f"(d[1]), "+f"(d[2]), "+f"(d[3])
        : "r"(a0), "r"(a1), "r"(a2), "r"(a3), "r"(b0), "r"(b1));
}

__device__ __forceinline__ void ldsm4(uint32_t* r, uint32_t addr) {
    asm volatile("ldmatrix.sync.aligned.m8n8.x4.shared.b16 {%0,%1,%2,%3}, [%4];"
        : "=r"(r[0]), "=r"(r[1]), "=r"(r[2]), "=r"(r[3]) : "r"(addr));
}

__device__ __forceinline__ void ldsm4t(uint32_t* r, uint32_t addr) {
    asm volatile("ldmatrix.sync.aligned.m8n8.x4.trans.shared.b16 {%0,%1,%2,%3}, [%4];"
        : "=r"(r[0]), "=r"(r[1]), "=r"(r[2]), "=r"(r[3]) : "r"(addr));
}

__device__ __forceinline__ uint32_t packh2(float lo, float hi) {
    __half2 h = __floats2half2_rn(lo, hi);
    return *(uint32_t*)&h;
}

// ---------------------------------------------------------------------------
// fp32 -> fp16 conversion pass over x + 4 weights. 8 floats per thread.
// Blocks [0,2048) -> x ; [2048+512*i) -> weight i. 2048 floats per block.
// ---------------------------------------------------------------------------
__global__ __launch_bounds__(256) void tohalf_kernel(
    const float* __restrict__ x,
    const float* __restrict__ wq, const float* __restrict__ wk,
    const float* __restrict__ wv, const float* __restrict__ wo,
    __half* __restrict__ xr,
    __half* __restrict__ wqr, __half* __restrict__ wkr,
    __half* __restrict__ wvr, __half* __restrict__ wor)
{
    const int bidx = blockIdx.x;
    const float* src;
    __half* dst;
    int off;
    if (bidx < 2048) { src = x; dst = xr; off = bidx; }
    else {
        const int i = (bidx - 2048) >> 9;
        off = (bidx - 2048) & 511;
        src = (i == 0) ? wq : (i == 1) ? wk : (i == 2) ? wv : wo;
        dst = (i == 0) ? wqr : (i == 1) ? wkr : (i == 2) ? wvr : wor;
    }
    const int base = off * 2048 + threadIdx.x * 8;
    float4 v0 = *(const float4*)(src + base);
    float4 v1 = *(const float4*)(src + base + 4);
    uint4 o;
    o.x = packh2(v0.x, v0.y); o.y = packh2(v0.z, v0.w);
    o.z = packh2(v1.x, v1.y); o.w = packh2(v1.z, v1.w);
    *(uint4*)(dst + base) = o;
}

// ---------------------------------------------------------------------------
// fp16 mma.sync GEMM: C[m][n] = sum_k A[m][k]*W[n][k]. M=4096,N=1024,K=1024.
// Tile 256x128, 8 warps, warp 64x64 (4m x 2n of 16-wide tiles).
// K-chunk 64 halfs (128B/row), XOR-swizzled 16B groups, 3 stages (48KB each),
// prefetch distance 2. ldmatrix fragments, m16n8k16 mma, fp32 accumulators.
// scatter=1 -> (B,H,S,dk) fp16; else fp32 row-major to CF.
// ---------------------------------------------------------------------------
#define GTM 256
#define GTN 128
#define GCHUNK 64
#define A_STG_H (GTM * GCHUNK)               // 16384 halfs = 32KB
#define B_STG_H (GTN * GCHUNK)               // 8192 halfs = 16KB
#define STG_H   (A_STG_H + B_STG_H)          // 24576 halfs = 48KB
#define GSTAGES 3
#define GEMM_SMEM (GSTAGES * STG_H * 2)      // 147456 B

__global__ __launch_bounds__(256, 1) void gemm_f16_kernel(
    const __half* __restrict__ A,
    const __half* __restrict__ W0, const __half* __restrict__ W1, const __half* __restrict__ W2,
    __half* __restrict__ C0, __half* __restrict__ C1, __half* __restrict__ C2,
    float* __restrict__ CF, int scatter)
{
    const __half* __restrict__ W = (blockIdx.z == 0) ? W0 : (blockIdx.z == 1) ? W1 : W2;
    __half* __restrict__ C       = (blockIdx.z == 0) ? C0 : (blockIdx.z == 1) ? C1 : C2;

    extern __shared__ __half smh[];

    const int tid  = threadIdx.x;
    const int wid  = tid >> 5;
    const int lane = tid & 31;
    const int g    = lane >> 2;
    const int t    = lane & 3;
    const int wm   = wid & 3;
    const int wn   = wid >> 2;
    const int nBase = blockIdx.x * GTN;
    const int mBase = blockIdx.y * GTM;

    float acc[4][8][4];
#pragma unroll
    for (int i = 0; i < 4; i++)
#pragma unroll
        for (int j = 0; j < 8; j++)
#pragma unroll
            for (int l = 0; l < 4; l++) acc[i][j][l] = 0.0f;

    const uint32_t smemA0 = smem_u32(smh);

    const int rowA = wm * 64 + (lane & 15);
    const int rowB = wn * 64 + (lane & 7) + ((lane >> 4) << 3);
    const int c4bitA = lane >> 4;
    const int c4bitB = (lane >> 3) & 1;
    const int lxor   = lane & 7;

    // issue 64-K chunk c into stage s; 16B = 8 halfs per group
    auto issue = [&](int c, int s) {
        const uint32_t st = smemA0 + (uint32_t)(s * STG_H) * 2u;
        // A: 256 rows x 8 groups = 2048 groups, 8 per thread
#pragma unroll
        for (int i = 0; i < 8; i++) {
            const int idx = tid + 256 * i;
            const int r = idx >> 3, cg = idx & 7;
            const uint32_t off = (uint32_t)(r * 128 + (((cg ^ (r & 7)) & 7) << 4));
            cp_async16(st + off, A + (size_t)(mBase + r) * DMODEL + c * GCHUNK + cg * 8);
        }
        // B: 128 rows x 8 groups = 1024 groups, 4 per thread
#pragma unroll
        for (int i = 0; i < 4; i++) {
            const int idx = tid + 256 * i;
            const int r = idx >> 3, cg = idx & 7;
            const uint32_t off = (uint32_t)(r * 128 + (((cg ^ (r & 7)) & 7) << 4));
            cp_async16(st + (uint32_t)A_STG_H * 2u + off,
                       W + (size_t)(nBase + r) * DMODEL + c * GCHUNK + cg * 8);
        }
    };

    issue(0, 0); CP_COMMIT();
    issue(1, 1); CP_COMMIT();

    const int NCHUNK = DMODEL / GCHUNK;   // 16
    for (int c = 0; c < NCHUNK; c++) {
        CP_WAIT(1);
        __syncthreads();
        if (c + 2 < NCHUNK) issue(c + 2, (c + 2) % GSTAGES);
        CP_COMMIT();

        const uint32_t Ast = smemA0 + (uint32_t)((c % GSTAGES) * STG_H) * 2u;
        const uint32_t Bst = Ast + (uint32_t)A_STG_H * 2u;

#pragma unroll
        for (int ks = 0; ks < 4; ks++) {             // 4 x k16
            const int xa = ((2 * ks + c4bitA) ^ lxor) & 7;
            const int xb = ((2 * ks + c4bitB) ^ lxor) & 7;

            uint32_t a[4][4];
#pragma unroll
            for (int mt = 0; mt < 4; mt++)
                ldsm4(a[mt], Ast + (uint32_t)((rowA + mt * 16) * 128 + xa * 16));

            uint32_t b[4][4];
#pragma unroll
            for (int ntp = 0; ntp < 4; ntp++)
                ldsm4(b[ntp], Bst + (uint32_t)((rowB + ntp * 16) * 128 + xb * 16));

#pragma unroll
            for (int mt = 0; mt < 4; mt++)
#pragma unroll
                for (int ntp = 0; ntp < 4; ntp++) {
                    mma_f16(acc[mt][2 * ntp],     a[mt][0], a[mt][1], a[mt][2], a[mt][3],
                            b[ntp][0], b[ntp][1]);
                    mma_f16(acc[mt][2 * ntp + 1], a[mt][0], a[mt][1], a[mt][2], a[mt][3],
                            b[ntp][2], b[ntp][3]);
                }
        }
    }

    // Epilogue: c0,c1 -> row r cols 2t,2t+1 ; c2,c3 -> row r+8
#pragma unroll
    for (int mt = 0; mt < 4; mt++) {
#pragma unroll
        for (int half = 0; half < 2; half++) {
            const int m = mBase + wm * 64 + mt * 16 + g + half * 8;
#pragma unroll
            for (int nt = 0; nt < 8; nt++) {
                const int n = nBase + wn * 64 + nt * 8 + 2 * t;
                const float vx = acc[mt][nt][half * 2 + 0];
                const float vy = acc[mt][nt][half * 2 + 1];
                if (scatter) {
                    const int b = m >> 11, s = m & 2047;
                    const int head = n >> 6, d0 = n & 63;
                    const uint32_t u = packh2(vx, vy);
                    *(uint32_t*)&C[(((size_t)((b << 4) + head) * S_LEN + s) * DK + d0)] = u;
                } else {
                    float2 v; v.x = vx; v.y = vy;
                    *(float2*)&CF[(size_t)m * DMODEL + n] = v;
                }
            }
        }
    }
}

// ---------------------------------------------------------------------------
// fp16 flash attention. CTA: 256 thr (8 warps), Q block 256 rows (32/warp),
// kv tile 64, 2-stage cp.async. Scalar Q/K fragments (padded stride 72 halfs,
// conflict-free), V via ldmatrix.x4.trans, P stays in registers:
// the m16n8 D-layout of QK IS the m16n8k16 A-layout for PV.
// ---------------------------------------------------------------------------
#define AKSTR   72                       // halfs per row (144B, conflict-free)
#define K_TILE_H (64 * AKSTR)            // 4608 halfs
#define ASTG_H  (2 * K_TILE_H)           // 9216 halfs (K then V)
#define SQ_OFF_H (2 * ASTG_H)            // 18432 halfs
#define SQW_H   (32 * AKSTR)             // 2304 halfs per warp
#define ATTN_SMEM ((SQ_OFF_H + 8 * SQW_H) * 2)   // 73728 B

__global__ __launch_bounds__(256) void attn_f16_kernel(
    const __half* __restrict__ Q, const __half* __restrict__ K,
    const __half* __restrict__ V, __half* __restrict__ Oatt)
{
    extern __shared__ __half smh[];

    const int tid  = threadIdx.x;
    const int wid  = tid >> 5;
    const int lane = tid & 31;
    const int g    = lane >> 2;
    const int t    = lane & 3;
    const int qb   = blockIdx.x;            // 0..7
    const int bh   = blockIdx.y;            // 0..31
    const int b    = bh >> 4;
    const int h    = bh & 15;

    const uint32_t smemB = smem_u32(smh);
    __half* sQw = smh + SQ_OFF_H + wid * SQW_H;

    // ---- Stage Q slice (32 rows/warp), pre-scaled by 1/8 (exact in fp16)
    {
        const __half* Qg = Q + ((size_t)bh * S_LEN + qb * 256 + wid * 32) * DK;
        const __half2 sc = __floats2half2_rn(0.125f, 0.125f);
#pragma unroll
        for (int i = 0; i < 8; i++) {
            const int idx = lane + 32 * i;      // 0..255 (32 rows x 8 groups)
            const int r = idx >> 3, cg = idx & 7;
            uint4 u = *(const uint4*)(Qg + r * DK + cg * 8);
            __half2* hp = (__half2*)&u;
            hp[0] = __hmul2(hp[0], sc); hp[1] = __hmul2(hp[1], sc);
            hp[2] = __hmul2(hp[2], sc); hp[3] = __hmul2(hp[3], sc);
            *(uint4*)(sQw + r * AKSTR + cg * 8) = u;
        }
        __syncwarp();
    }

    float o_[2][8][4];
#pragma unroll
    for (int mt = 0; mt < 2; mt++)
#pragma unroll
        for (int nt = 0; nt < 8; nt++)
#pragma unroll
            for (int l = 0; l < 4; l++) o_[mt][nt][l] = 0.0f;
    float mrow[2][2] = {{-1e30f, -1e30f}, {-1e30f, -1e30f}};
    float lrow[2][2] = {{0.0f, 0.0f}, {0.0f, 0.0f}};

    const __half* Kg = K + (size_t)bh * S_LEN * DK;
    const __half* Vg = V + (size_t)bh * S_LEN * DK;

    // K/V tile loader: 64 rows x 8 groups each = 512+512 groups, 4/thread
    auto issue = [&](int kv, int st) {
        const uint32_t stb = smemB + (uint32_t)(st * ASTG_H) * 2u;
        const __half* kS = Kg + (size_t)kv * 64 * DK;
        const __half* vS = Vg + (size_t)kv * 64 * DK;
#pragma unroll
        for (int i = 0; i < 2; i++) {
            const int idx = tid + 256 * i;      // 0..511
            const int r = idx >> 3, cg = idx & 7;
            cp_async16(stb + (uint32_t)(r * 144 + cg * 16), kS + r * DK + cg * 8);
            cp_async16(stb + (uint32_t)K_TILE_H * 2u + (uint32_t)(r * 144 + cg * 16),
                       vS + r * DK + cg * 8);
        }
    };

    issue(0, 0); CP_COMMIT();

    const int NKV = S_LEN / 64;   // 32
    for (int kv = 0; kv < NKV; kv++) {
        CP_WAIT(0);
        __syncthreads();
        if (kv + 1 < NKV) issue(kv + 1, (kv + 1) & 1);
        CP_COMMIT();

        const __half* sK = smh + (kv & 1) * ASTG_H;
        const uint32_t Vbase = smemB + (uint32_t)((kv & 1) * ASTG_H + K_TILE_H) * 2u;

        // ---- scores S = (Q/8) K^T   (32 x 64 per warp, m16n8k16)
        float s_[2][8][4];
#pragma unroll
        for (int mt = 0; mt < 2; mt++)
#pragma unroll
            for (int nt = 0; nt < 8; nt++)
#pragma unroll
                for (int l = 0; l < 4; l++) s_[mt][nt][l] = 0.0f;

#pragma unroll
        for (int ks = 0; ks < 4; ks++) {
            uint32_t a[2][4];
#pragma unroll
            for (int mt = 0; mt < 2; mt++) {
                const __half* Ar = sQw + (mt * 16 + g) * AKSTR + ks * 16 + 2 * t;
                a[mt][0] = *(const uint32_t*)(Ar);
                a[mt][1] = *(const uint32_t*)(Ar + 8 * AKSTR);
                a[mt][2] = *(const uint32_t*)(Ar + 8);
                a[mt][3] = *(const uint32_t*)(Ar + 8 * AKSTR + 8);
            }
#pragma unroll
            for (int nt = 0; nt < 8; nt++) {
                const __half* Kr = sK + (nt * 8 + g) * AKSTR + ks * 16 + 2 * t;
                uint32_t b0 = *(const uint32_t*)(Kr);
                uint32_t b1 = *(const uint32_t*)(Kr + 8);
                mma_f16(s_[0][nt], a[0][0], a[0][1], a[0][2], a[0][3], b0, b1);
                mma_f16(s_[1][nt], a[1][0], a[1][1], a[1][2], a[1][3], b0, b1);
            }
        }

        // ---- online softmax per m-tile (fp32)
#pragma unroll
        for (int mt = 0; mt < 2; mt++) {
            float mx0 = -1e30f, mx1 = -1e30f;
#pragma unroll
            for (int nt = 0; nt < 8; nt++) {
                mx0 = fmaxf(mx0, fmaxf(s_[mt][nt][0], s_[mt][nt][1]));
                mx1 = fmaxf(mx1, fmaxf(s_[mt][nt][2], s_[mt][nt][3]));
            }
            mx0 = fmaxf(mx0, __shfl_xor_sync(0xffffffffu, mx0, 1));
            mx0 = fmaxf(mx0, __shfl_xor_sync(0xffffffffu, mx0, 2));
            mx1 = fmaxf(mx1, __shfl_xor_sync(0xffffffffu, mx1, 1));
            mx1 = fmaxf(mx1, __shfl_xor_sync(0xffffffffu, mx1, 2));

            float mn0 = fmaxf(mrow[mt][0], mx0), mn1 = fmaxf(mrow[mt][1], mx1);
            float al0 = __expf(mrow[mt][0] - mn0), al1 = __expf(mrow[mt][1] - mn1);
            mrow[mt][0] = mn0; mrow[mt][1] = mn1;

            float s0 = 0.0f, s1 = 0.0f;
#pragma unroll
            for (int nt = 0; nt < 8; nt++) {
                s_[mt][nt][0] = __expf(s_[mt][nt][0] - mn0); s0 += s_[mt][nt][0];
                s_[mt][nt][1] = __expf(s_[mt][nt][1] - mn0); s0 += s_[mt][nt][1];
                s_[mt][nt][2] = __expf(s_[mt][nt][2] - mn1); s1 += s_[mt][nt][2];
                s_[mt][nt][3] = __expf(s_[mt][nt][3] - mn1); s1 += s_[mt][nt][3];
            }
            s0 += __shfl_xor_sync(0xffffffffu, s0, 1);
            s0 += __shfl_xor_sync(0xffffffffu, s0, 2);
            s1 += __shfl_xor_sync(0xffffffffu, s1, 1);
            s1 += __shfl_xor_sync(0xffffffffu, s1, 2);
            lrow[mt][0] = lrow[mt][0] * al0 + s0;
            lrow[mt][1] = lrow[mt][1] * al1 + s1;

#pragma unroll
            for (int nt = 0; nt < 8; nt++) {
                o_[mt][nt][0] *= al0; o_[mt][nt][1] *= al0;
                o_[mt][nt][2] *= al1; o_[mt][nt][3] *= al1;
            }
        }

        // ---- O += P V : P packed reg->reg (D-layout == A-layout for k16),
        //      V b-frags via ldmatrix.x4.trans
#pragma unroll
        for (int kt = 0; kt < 4; kt++) {
            uint32_t ap[2][4];
#pragma unroll
            for (int mt = 0; mt < 2; mt++) {
                ap[mt][0] = packh2(s_[mt][2 * kt][0],     s_[mt][2 * kt][1]);
                ap[mt][1] = packh2(s_[mt][2 * kt][2],     s_[mt][2 * kt][3]);
                ap[mt][2] = packh2(s_[mt][2 * kt + 1][0], s_[mt][2 * kt + 1][1]);
                ap[mt][3] = packh2(s_[mt][2 * kt + 1][2], s_[mt][2 * kt + 1][3]);
            }
            const int kvrow = kt * 16 + (lane & 15);
#pragma unroll
            for (int ntp = 0; ntp < 4; ntp++) {
                const int colb = ntp * 16 + ((lane >> 4) << 3);
                uint32_t vv[4];
                ldsm4t(vv, Vbase + (uint32_t)(kvrow * 144 + colb * 2));
                mma_f16(o_[0][2 * ntp],     ap[0][0], ap[0][1], ap[0][2], ap[0][3], vv[0], vv[1]);
                mma_f16(o_[0][2 * ntp + 1], ap[0][0], ap[0][1], ap[0][2], ap[0][3], vv[2], vv[3]);
                mma_f16(o_[1][2 * ntp],     ap[1][0], ap[1][1], ap[1][2], ap[1][3], vv[0], vv[1]);
                mma_f16(o_[1][2 * ntp + 1], ap[1][0], ap[1][1], ap[1][2], ap[1][3], vv[2], vv[3]);
            }
        }
    }

    // ---- epilogue: normalize, write fp16 (B,S,D)
#pragma unroll
    for (int mt = 0; mt < 2; mt++) {
        const float inv0 = 1.0f / lrow[mt][0], inv1 = 1.0f / lrow[mt][1];
        const int row0 = qb * 256 + wid * 32 + mt * 16 + g;
#pragma unroll
        for (int nt = 0; nt < 8; nt++) {
            const int col = h * DK + nt * 8 + 2 * t;
            const uint32_t u0 = packh2(o_[mt][nt][0] * inv0, o_[mt][nt][1] * inv0);
            const uint32_t u1 = packh2(o_[mt][nt][2] * inv1, o_[mt][nt][3] * inv1);
            *(uint32_t*)&Oatt[((size_t)b * S_LEN + row0) * DMODEL + col]     = u0;
            *(uint32_t*)&Oatt[((size_t)b * S_LEN + row0 + 8) * DMODEL + col] = u1;
        }
    }
}

// ---------------------------------------------------------------------------
extern "C" void kernel_launch(void* const* d_in, const int* in_sizes, int n_in,
                              void* d_out, int out_size)
{
    const float* x  = (const float*)d_in[0];
    const float* Wq = (const float*)d_in[1];
    const float* Wk = (const float*)d_in[2];
    const float* Wv = (const float*)d_in[3];
    const float* Wo = (const float*)d_in[4];
    float* out = (float*)d_out;

    __half *qp, *kp, *vp, *attp, *hp;
    cudaGetSymbolAddress((void**)&qp,   g_q);
    cudaGetSymbolAddress((void**)&kp,   g_k);
    cudaGetSymbolAddress((void**)&vp,   g_v);
    cudaGetSymbolAddress((void**)&attp, g_att);
    cudaGetSymbolAddress((void**)&hp,   g_half);

    __half* xr  = hp;                       // 4M halfs
    __half* wqr = hp + 4 * 1024 * 1024;
    __half* wkr = hp + 5 * 1024 * 1024;
    __half* wvr = hp + 6 * 1024 * 1024;
    __half* wor = hp + 7 * 1024 * 1024;

    // 0) fp32 -> fp16 conversion of all GEMM operands
    tohalf_kernel<<<4096, 256>>>(x, Wq, Wk, Wv, Wo, xr, wqr, wkr, wvr, wor);

    cudaFuncSetAttribute(gemm_f16_kernel, cudaFuncAttributeMaxDynamicSharedMemorySize,
                         GEMM_SMEM);
    cudaFuncSetAttribute(attn_f16_kernel, cudaFuncAttributeMaxDynamicSharedMemorySize,
                         ATTN_SMEM);

    // 1) Fused QKV projections (fp16 mma), scatter to (B,H,S,dk) fp16
    dim3 gQKV(DMODEL / GTN, M_TOTAL / GTM, 3);
    gemm_f16_kernel<<<gQKV, 256, GEMM_SMEM>>>(xr, wqr, wkr, wvr, qp, kp, vp,
                                              nullptr, 1);

    // 2) Flash attention (fp16 mma) -> (B,S,D) fp16
    dim3 gA(S_LEN / 256, BATCH * NHEADS);
    attn_f16_kernel<<<gA, 256, ATTN_SMEM>>>(qp, kp, vp, attp);

    // 3) Output projection (fp16 mma) -> fp32 d_out
    dim3 gO(DMODEL / GTN, M_TOTAL / GTM, 1);
    gemm_f16_kernel<<<gO, 256, GEMM_SMEM>>>(attp, wor, wor, wor,
                                            nullptr, nullptr, nullptr, out, 0);
}

// round 15
// speedup vs baseline: 2.0612x; 1.0682x over previous
#include <cuda_runtime.h>
#include <cuda_fp16.h>
#include <cstdint>

// Problem constants
#define S_LEN    2048
#define DMODEL   1024
#define NHEADS   16
#define DK       64
#define BATCH    2
#define M_TOTAL  (BATCH * S_LEN)   // 4096

// Scratch (allocation-free rule: __device__ globals)
__device__ __half g_q[BATCH * NHEADS * S_LEN * DK];    // (B,H,S,dk) fp16, pre-scaled
__device__ __half g_k[BATCH * NHEADS * S_LEN * DK];
__device__ __half g_v[BATCH * NHEADS * S_LEN * DK];
__device__ __half g_att[BATCH * S_LEN * DMODEL];       // (B,S,D) fp16
__device__ __half g_half[8 * 1024 * 1024];             // fp16 x + 4 weights

// Q pre-scale folded into QKV epilogue: (1/sqrt(dk)) * log2(e)
#define QSCALE 0.1803368801f

// ---------------------------------------------------------------------------
// Helpers
// ---------------------------------------------------------------------------
__device__ __forceinline__ uint32_t smem_u32(const void* p) {
    uint32_t a;
    asm("{ .reg .u64 t; cvta.to.shared.u64 t, %1; cvt.u32.u64 %0, t; }"
        : "=r"(a) : "l"(p));
    return a;
}

__device__ __forceinline__ void cp_async16(uint32_t s, const void* g) {
    asm volatile("cp.async.cg.shared.global [%0], [%1], 16;" :: "r"(s), "l"(g));
}
#define CP_COMMIT() asm volatile("cp.async.commit_group;" ::: "memory")
#define CP_WAIT(n)  asm volatile("cp.async.wait_group %0;" :: "n"(n) : "memory")

// D(16x8) += A(16x16,row) * B(16x8,col) -- fp16 operands, fp32 accum
__device__ __forceinline__ void mma_f16(float* d,
                                        uint32_t a0, uint32_t a1, uint32_t a2, uint32_t a3,
                                        uint32_t b0, uint32_t b1) {
    asm volatile(
        "mma.sync.aligned.m16n8k16.row.col.f32.f16.f16.f32 "
        "{%0,%1,%2,%3}, {%4,%5,%6,%7}, {%8,%9}, {%0,%1,%2,%3};"
        : "+f"(d[0]), "+f"(d[1]), "+f"(d[2]), "+f"(d[3])
        : "r"(a0), "r"(a1), "r"(a2), "r"(a3), "r"(b0), "r"(b1));
}

__device__ __forceinline__ void ldsm4(uint32_t* r, uint32_t addr) {
    asm volatile("ldmatrix.sync.aligned.m8n8.x4.shared.b16 {%0,%1,%2,%3}, [%4];"
        : "=r"(r[0]), "=r"(r[1]), "=r"(r[2]), "=r"(r[3]) : "r"(addr));
}

__device__ __forceinline__ void ldsm4t(uint32_t* r, uint32_t addr) {
    asm volatile("ldmatrix.sync.aligned.m8n8.x4.trans.shared.b16 {%0,%1,%2,%3}, [%4];"
        : "=r"(r[0]), "=r"(r[1]), "=r"(r[2]), "=r"(r[3]) : "r"(addr));
}

__device__ __forceinline__ uint32_t packh2(float lo, float hi) {
    __half2 h = __floats2half2_rn(lo, hi);
    return *(uint32_t*)&h;
}

__device__ __forceinline__ float ex2f(float x) {
    float r;
    asm("ex2.approx.f32 %0, %1;" : "=f"(r) : "f"(x));
    return r;
}

// ---------------------------------------------------------------------------
// fp32 -> fp16 conversion pass over x + 4 weights. 8 floats per thread.
// ---------------------------------------------------------------------------
__global__ __launch_bounds__(256) void tohalf_kernel(
    const float* __restrict__ x,
    const float* __restrict__ wq, const float* __restrict__ wk,
    const float* __restrict__ wv, const float* __restrict__ wo,
    __half* __restrict__ xr,
    __half* __restrict__ wqr, __half* __restrict__ wkr,
    __half* __restrict__ wvr, __half* __restrict__ wor)
{
    const int bidx = blockIdx.x;
    const float* src;
    __half* dst;
    int off;
    if (bidx < 2048) { src = x; dst = xr; off = bidx; }
    else {
        const int i = (bidx - 2048) >> 9;
        off = (bidx - 2048) & 511;
        src = (i == 0) ? wq : (i == 1) ? wk : (i == 2) ? wv : wo;
        dst = (i == 0) ? wqr : (i == 1) ? wkr : (i == 2) ? wvr : wor;
    }
    const int base = off * 2048 + threadIdx.x * 8;
    float4 v0 = *(const float4*)(src + base);
    float4 v1 = *(const float4*)(src + base + 4);
    uint4 o;
    o.x = packh2(v0.x, v0.y); o.y = packh2(v0.z, v0.w);
    o.z = packh2(v1.x, v1.y); o.w = packh2(v1.z, v1.w);
    *(uint4*)(dst + base) = o;
}

// ---------------------------------------------------------------------------
// fp16 mma.sync GEMM: tile 256x128, warp 64x64. K-chunk 128 halfs as two
// 128B-row swizzled panels per operand; 2 stages (96KB each) = 192KB smem.
// ldmatrix fragments, m16n8k16, fp32 accum. Accumulation order unchanged.
// scatter=1 -> (B,H,S,dk) fp16 (Q gets QSCALE); else fp32 row-major to CF.
// ---------------------------------------------------------------------------
#define GTM 256
#define GTN 128
#define GCHUNK 128
#define A_PANEL_H (GTM * 64)                  // 16384 halfs = 32KB
#define B_PANEL_H (GTN * 64)                  // 8192 halfs = 16KB
#define A_STG_H (2 * A_PANEL_H)               // 64KB
#define B_STG_H (2 * B_PANEL_H)               // 32KB
#define STG_H   (A_STG_H + B_STG_H)           // 49152 halfs = 96KB
#define GSTAGES 2
#define GEMM_SMEM (GSTAGES * STG_H * 2)       // 196608 B

__global__ __launch_bounds__(256, 1) void gemm_f16_kernel(
    const __half* __restrict__ A,
    const __half* __restrict__ W0, const __half* __restrict__ W1, const __half* __restrict__ W2,
    __half* __restrict__ C0, __half* __restrict__ C1, __half* __restrict__ C2,
    float* __restrict__ CF, int scatter)
{
    const __half* __restrict__ W = (blockIdx.z == 0) ? W0 : (blockIdx.z == 1) ? W1 : W2;
    __half* __restrict__ C       = (blockIdx.z == 0) ? C0 : (blockIdx.z == 1) ? C1 : C2;

    extern __shared__ __half smh[];

    const int tid  = threadIdx.x;
    const int wid  = tid >> 5;
    const int lane = tid & 31;
    const int g    = lane >> 2;
    const int t    = lane & 3;
    const int wm   = wid & 3;
    const int wn   = wid >> 2;
    const int nBase = blockIdx.x * GTN;
    const int mBase = blockIdx.y * GTM;

    float acc[4][8][4];
#pragma unroll
    for (int i = 0; i < 4; i++)
#pragma unroll
        for (int j = 0; j < 8; j++)
#pragma unroll
            for (int l = 0; l < 4; l++) acc[i][j][l] = 0.0f;

    const uint32_t smemA0 = smem_u32(smh);

    const int rowA = wm * 64 + (lane & 15);
    const int rowB = wn * 64 + (lane & 7) + ((lane >> 4) << 3);
    const int c4bitA = lane >> 4;
    const int c4bitB = (lane >> 3) & 1;
    const int lxor   = lane & 7;

    // issue 128-K chunk c into stage s; groups of 8 halfs (16B)
    auto issue = [&](int c, int s) {
        const uint32_t st = smemA0 + (uint32_t)(s * STG_H) * 2u;
        // A: 256 rows x 16 groups = 4096 groups, 16 per thread
#pragma unroll
        for (int i = 0; i < 16; i++) {
            const int idx = tid + 256 * i;
            const int r = idx >> 4, cg = idx & 15;
            const int pan = cg >> 3, c8 = cg & 7;
            const uint32_t off =
                (uint32_t)(pan * A_PANEL_H * 2 + r * 128 + (((c8 ^ (r & 7)) & 7) << 4));
            cp_async16(st + off, A + (size_t)(mBase + r) * DMODEL + c * GCHUNK + cg * 8);
        }
        // B: 128 rows x 16 groups = 2048 groups, 8 per thread
#pragma unroll
        for (int i = 0; i < 8; i++) {
            const int idx = tid + 256 * i;
            const int r = idx >> 4, cg = idx & 15;
            const int pan = cg >> 3, c8 = cg & 7;
            const uint32_t off =
                (uint32_t)(pan * B_PANEL_H * 2 + r * 128 + (((c8 ^ (r & 7)) & 7) << 4));
            cp_async16(st + (uint32_t)A_STG_H * 2u + off,
                       W + (size_t)(nBase + r) * DMODEL + c * GCHUNK + cg * 8);
        }
    };

    issue(0, 0); CP_COMMIT();

    const int NCHUNK = DMODEL / GCHUNK;   // 8
    for (int c = 0; c < NCHUNK; c++) {
        CP_WAIT(0);
        __syncthreads();
        if (c + 1 < NCHUNK) issue(c + 1, (c + 1) & 1);
        CP_COMMIT();

        const uint32_t Ast = smemA0 + (uint32_t)((c & 1) * STG_H) * 2u;
        const uint32_t Bst = Ast + (uint32_t)A_STG_H * 2u;

#pragma unroll
        for (int ks = 0; ks < 8; ks++) {             // 8 x k16
            const uint32_t panA = (uint32_t)((ks >> 2) * A_PANEL_H) * 2u;
            const uint32_t panB = (uint32_t)((ks >> 2) * B_PANEL_H) * 2u;
            const int k2 = ks & 3;
            const int xa = ((2 * k2 + c4bitA) ^ lxor) & 7;
            const int xb = ((2 * k2 + c4bitB) ^ lxor) & 7;

            uint32_t a[4][4];
#pragma unroll
            for (int mt = 0; mt < 4; mt++)
                ldsm4(a[mt], Ast + panA + (uint32_t)((rowA + mt * 16) * 128 + xa * 16));

            uint32_t b[4][4];
#pragma unroll
            for (int ntp = 0; ntp < 4; ntp++)
                ldsm4(b[ntp], Bst + panB + (uint32_t)((rowB + ntp * 16) * 128 + xb * 16));

#pragma unroll
            for (int mt = 0; mt < 4; mt++)
#pragma unroll
                for (int ntp = 0; ntp < 4; ntp++) {
                    mma_f16(acc[mt][2 * ntp],     a[mt][0], a[mt][1], a[mt][2], a[mt][3],
                            b[ntp][0], b[ntp][1]);
                    mma_f16(acc[mt][2 * ntp + 1], a[mt][0], a[mt][1], a[mt][2], a[mt][3],
                            b[ntp][2], b[ntp][3]);
                }
        }
    }

    // Epilogue; Q (scatter && z==0) gets QSCALE folded in (fp32, free)
    const float qs = (scatter && blockIdx.z == 0) ? QSCALE : 1.0f;
#pragma unroll
    for (int mt = 0; mt < 4; mt++) {
#pragma unroll
        for (int half = 0; half < 2; half++) {
            const int m = mBase + wm * 64 + mt * 16 + g + half * 8;
#pragma unroll
            for (int nt = 0; nt < 8; nt++) {
                const int n = nBase + wn * 64 + nt * 8 + 2 * t;
                const float vx = acc[mt][nt][half * 2 + 0];
                const float vy = acc[mt][nt][half * 2 + 1];
                if (scatter) {
                    const int b = m >> 11, s = m & 2047;
                    const int head = n >> 6, d0 = n & 63;
                    const uint32_t u = packh2(vx * qs, vy * qs);
                    *(uint32_t*)&C[(((size_t)((b << 4) + head) * S_LEN + s) * DK + d0)] = u;
                } else {
                    float2 v; v.x = vx; v.y = vy;
                    *(float2*)&CF[(size_t)m * DMODEL + n] = v;
                }
            }
        }
    }
}

// ---------------------------------------------------------------------------
// fp16 flash attention. CTA: 256 thr (8 warps), Q block 256 rows (32/warp),
// kv tile 64, 2-stage cp.async. Q/K fragments via ldmatrix.x4 on padded
// 144B rows (affine addresses, conflict-free: bank = 4*row mod 32 per phase).
// Q arrives pre-scaled by log2e/sqrt(dk); softmax in exp2 domain (bare ex2).
// P stays in registers (QK D-layout == PV A-layout for k16).
// V via ldmatrix.x4.trans.
// ---------------------------------------------------------------------------
#define AKSTR   72                       // halfs per row (144B)
#define K_TILE_H (64 * AKSTR)            // 4608 halfs
#define ASTG_H  (2 * K_TILE_H)           // 9216 halfs (K then V)
#define SQ_OFF_H (2 * ASTG_H)            // 18432 halfs
#define SQW_H   (32 * AKSTR)             // 2304 halfs per warp
#define ATTN_SMEM ((SQ_OFF_H + 8 * SQW_H) * 2)   // 73728 B

__global__ __launch_bounds__(256) void attn_f16_kernel(
    const __half* __restrict__ Q, const __half* __restrict__ K,
    const __half* __restrict__ V, __half* __restrict__ Oatt)
{
    extern __shared__ __half smh[];

    const int tid  = threadIdx.x;
    const int wid  = tid >> 5;
    const int lane = tid & 31;
    const int g    = lane >> 2;
    const int t    = lane & 3;
    const int qb   = blockIdx.x;            // 0..7
    const int bh   = blockIdx.y;            // 0..31
    const int b    = bh >> 4;
    const int h    = bh & 15;

    const uint32_t smemB = smem_u32(smh);
    const uint32_t sqwB  = smemB + (uint32_t)(SQ_OFF_H + wid * SQW_H) * 2u;
    __half* sQw = smh + SQ_OFF_H + wid * SQW_H;

    // ---- Stage Q slice (32 rows/warp) into padded rows (already scaled)
    {
        const __half* Qg = Q + ((size_t)bh * S_LEN + qb * 256 + wid * 32) * DK;
#pragma unroll
        for (int i = 0; i < 8; i++) {
            const int idx = lane + 32 * i;      // 32 rows x 8 groups
            const int r = idx >> 3, cg = idx & 7;
            *(uint4*)(sQw + r * AKSTR + cg * 8) = *(const uint4*)(Qg + r * DK + cg * 8);
        }
        __syncwarp();
    }

    float o_[2][8][4];
#pragma unroll
    for (int mt = 0; mt < 2; mt++)
#pragma unroll
        for (int nt = 0; nt < 8; nt++)
#pragma unroll
            for (int l = 0; l < 4; l++) o_[mt][nt][l] = 0.0f;
    float mrow[2][2] = {{-1e30f, -1e30f}, {-1e30f, -1e30f}};
    float lrow[2][2] = {{0.0f, 0.0f}, {0.0f, 0.0f}};

    const __half* Kg = K + (size_t)bh * S_LEN * DK;
    const __half* Vg = V + (size_t)bh * S_LEN * DK;

    auto issue = [&](int kv, int st) {
        const uint32_t stb = smemB + (uint32_t)(st * ASTG_H) * 2u;
        const __half* kS = Kg + (size_t)kv * 64 * DK;
        const __half* vS = Vg + (size_t)kv * 64 * DK;
#pragma unroll
        for (int i = 0; i < 2; i++) {
            const int idx = tid + 256 * i;      // 0..511
            const int r = idx >> 3, cg = idx & 7;
            cp_async16(stb + (uint32_t)(r * 144 + cg * 16), kS + r * DK + cg * 8);
            cp_async16(stb + (uint32_t)K_TILE_H * 2u + (uint32_t)(r * 144 + cg * 16),
                       vS + r * DK + cg * 8);
        }
    };

    issue(0, 0); CP_COMMIT();

    // ldmatrix lane bases
    const uint32_t qoff = (uint32_t)((lane & 15) * 144 + ((lane >> 4) << 4));
    const uint32_t koff = (uint32_t)(((lane & 7) + ((lane >> 4) << 3)) * 144
                                     + (((lane >> 3) & 1) << 4));

    const int NKV = S_LEN / 64;   // 32
    for (int kv = 0; kv < NKV; kv++) {
        CP_WAIT(0);
        __syncthreads();
        if (kv + 1 < NKV) issue(kv + 1, (kv + 1) & 1);
        CP_COMMIT();

        const uint32_t Kst = smemB + (uint32_t)((kv & 1) * ASTG_H) * 2u;
        const uint32_t Vbase = Kst + (uint32_t)K_TILE_H * 2u;

        // ---- scores S = Q' K^T (log2 domain), 32x64/warp, ldmatrix frags
        float s_[2][8][4];
#pragma unroll
        for (int mt = 0; mt < 2; mt++)
#pragma unroll
            for (int nt = 0; nt < 8; nt++)
#pragma unroll
                for (int l = 0; l < 4; l++) s_[mt][nt][l] = 0.0f;

#pragma unroll
        for (int ks = 0; ks < 4; ks++) {
            uint32_t a[2][4];
            ldsm4(a[0], sqwB + qoff + (uint32_t)(ks * 32));
            ldsm4(a[1], sqwB + qoff + (uint32_t)(16 * 144 + ks * 32));
            uint32_t bb[4][4];
#pragma unroll
            for (int ntp = 0; ntp < 4; ntp++)
                ldsm4(bb[ntp], Kst + koff + (uint32_t)(ntp * 16 * 144 + ks * 32));
#pragma unroll
            for (int ntp = 0; ntp < 4; ntp++) {
                mma_f16(s_[0][2 * ntp],     a[0][0], a[0][1], a[0][2], a[0][3],
                        bb[ntp][0], bb[ntp][1]);
                mma_f16(s_[0][2 * ntp + 1], a[0][0], a[0][1], a[0][2], a[0][3],
                        bb[ntp][2], bb[ntp][3]);
                mma_f16(s_[1][2 * ntp],     a[1][0], a[1][1], a[1][2], a[1][3],
                        bb[ntp][0], bb[ntp][1]);
                mma_f16(s_[1][2 * ntp + 1], a[1][0], a[1][1], a[1][2], a[1][3],
                        bb[ntp][2], bb[ntp][3]);
            }
        }

        // ---- online softmax per m-tile (exp2 domain, fp32)
#pragma unroll
        for (int mt = 0; mt < 2; mt++) {
            float mx0 = -1e30f, mx1 = -1e30f;
#pragma unroll
            for (int nt = 0; nt < 8; nt++) {
                mx0 = fmaxf(mx0, fmaxf(s_[mt][nt][0], s_[mt][nt][1]));
                mx1 = fmaxf(mx1, fmaxf(s_[mt][nt][2], s_[mt][nt][3]));
            }
            mx0 = fmaxf(mx0, __shfl_xor_sync(0xffffffffu, mx0, 1));
            mx0 = fmaxf(mx0, __shfl_xor_sync(0xffffffffu, mx0, 2));
            mx1 = fmaxf(mx1, __shfl_xor_sync(0xffffffffu, mx1, 1));
            mx1 = fmaxf(mx1, __shfl_xor_sync(0xffffffffu, mx1, 2));

            float mn0 = fmaxf(mrow[mt][0], mx0), mn1 = fmaxf(mrow[mt][1], mx1);
            float al0 = ex2f(mrow[mt][0] - mn0), al1 = ex2f(mrow[mt][1] - mn1);
            mrow[mt][0] = mn0; mrow[mt][1] = mn1;

            float s0 = 0.0f, s1 = 0.0f;
#pragma unroll
            for (int nt = 0; nt < 8; nt++) {
                s_[mt][nt][0] = ex2f(s_[mt][nt][0] - mn0); s0 += s_[mt][nt][0];
                s_[mt][nt][1] = ex2f(s_[mt][nt][1] - mn0); s0 += s_[mt][nt][1];
                s_[mt][nt][2] = ex2f(s_[mt][nt][2] - mn1); s1 += s_[mt][nt][2];
                s_[mt][nt][3] = ex2f(s_[mt][nt][3] - mn1); s1 += s_[mt][nt][3];
            }
            s0 += __shfl_xor_sync(0xffffffffu, s0, 1);
            s0 += __shfl_xor_sync(0xffffffffu, s0, 2);
            s1 += __shfl_xor_sync(0xffffffffu, s1, 1);
            s1 += __shfl_xor_sync(0xffffffffu, s1, 2);
            lrow[mt][0] = lrow[mt][0] * al0 + s0;
            lrow[mt][1] = lrow[mt][1] * al1 + s1;

#pragma unroll
            for (int nt = 0; nt < 8; nt++) {
                o_[mt][nt][0] *= al0; o_[mt][nt][1] *= al0;
                o_[mt][nt][2] *= al1; o_[mt][nt][3] *= al1;
            }
        }

        // ---- O += P V : P packed reg->reg, V b-frags via ldmatrix.trans
#pragma unroll
        for (int kt = 0; kt < 4; kt++) {
            uint32_t ap[2][4];
#pragma unroll
            for (int mt = 0; mt < 2; mt++) {
                ap[mt][0] = packh2(s_[mt][2 * kt][0],     s_[mt][2 * kt][1]);
                ap[mt][1] = packh2(s_[mt][2 * kt][2],     s_[mt][2 * kt][3]);
                ap[mt][2] = packh2(s_[mt][2 * kt + 1][0], s_[mt][2 * kt + 1][1]);
                ap[mt][3] = packh2(s_[mt][2 * kt + 1][2], s_[mt][2 * kt + 1][3]);
            }
            const int kvrow = kt * 16 + (lane & 15);
#pragma unroll
            for (int ntp = 0; ntp < 4; ntp++) {
                const int colb = ntp * 16 + ((lane >> 4) << 3);
                uint32_t vv[4];
                ldsm4t(vv, Vbase + (uint32_t)(kvrow * 144 + colb * 2));
                mma_f16(o_[0][2 * ntp],     ap[0][0], ap[0][1], ap[0][2], ap[0][3], vv[0], vv[1]);
                mma_f16(o_[0][2 * ntp + 1], ap[0][0], ap[0][1], ap[0][2], ap[0][3], vv[2], vv[3]);
                mma_f16(o_[1][2 * ntp],     ap[1][0], ap[1][1], ap[1][2], ap[1][3], vv[0], vv[1]);
                mma_f16(o_[1][2 * ntp + 1], ap[1][0], ap[1][1], ap[1][2], ap[1][3], vv[2], vv[3]);
            }
        }
    }

    // ---- epilogue: normalize, write fp16 (B,S,D)
#pragma unroll
    for (int mt = 0; mt < 2; mt++) {
        const float inv0 = 1.0f / lrow[mt][0], inv1 = 1.0f / lrow[mt][1];
        const int row0 = qb * 256 + wid * 32 + mt * 16 + g;
#pragma unroll
        for (int nt = 0; nt < 8; nt++) {
            const int col = h * DK + nt * 8 + 2 * t;
            const uint32_t u0 = packh2(o_[mt][nt][0] * inv0, o_[mt][nt][1] * inv0);
            const uint32_t u1 = packh2(o_[mt][nt][2] * inv1, o_[mt][nt][3] * inv1);
            *(uint32_t*)&Oatt[((size_t)b * S_LEN + row0) * DMODEL + col]     = u0;
            *(uint32_t*)&Oatt[((size_t)b * S_LEN + row0 + 8) * DMODEL + col] = u1;
        }
    }
}

// ---------------------------------------------------------------------------
extern "C" void kernel_launch(void* const* d_in, const int* in_sizes, int n_in,
                              void* d_out, int out_size)
{
    const float* x  = (const float*)d_in[0];
    const float* Wq = (const float*)d_in[1];
    const float* Wk = (const float*)d_in[2];
    const float* Wv = (const float*)d_in[3];
    const float* Wo = (const float*)d_in[4];
    float* out = (float*)d_out;

    __half *qp, *kp, *vp, *attp, *hp;
    cudaGetSymbolAddress((void**)&qp,   g_q);
    cudaGetSymbolAddress((void**)&kp,   g_k);
    cudaGetSymbolAddress((void**)&vp,   g_v);
    cudaGetSymbolAddress((void**)&attp, g_att);
    cudaGetSymbolAddress((void**)&hp,   g_half);

    __half* xr  = hp;
    __half* wqr = hp + 4 * 1024 * 1024;
    __half* wkr = hp + 5 * 1024 * 1024;
    __half* wvr = hp + 6 * 1024 * 1024;
    __half* wor = hp + 7 * 1024 * 1024;

    // 0) fp32 -> fp16 conversion of all GEMM operands
    tohalf_kernel<<<4096, 256>>>(x, Wq, Wk, Wv, Wo, xr, wqr, wkr, wvr, wor);

    cudaFuncSetAttribute(gemm_f16_kernel, cudaFuncAttributeMaxDynamicSharedMemorySize,
                         GEMM_SMEM);
    cudaFuncSetAttribute(attn_f16_kernel, cudaFuncAttributeMaxDynamicSharedMemorySize,
                         ATTN_SMEM);

    // 1) Fused QKV projections (fp16 mma), scatter to (B,H,S,dk); Q pre-scaled
    dim3 gQKV(DMODEL / GTN, M_TOTAL / GTM, 3);
    gemm_f16_kernel<<<gQKV, 256, GEMM_SMEM>>>(xr, wqr, wkr, wvr, qp, kp, vp,
                                              nullptr, 1);

    // 2) Flash attention (fp16 mma, exp2 softmax) -> (B,S,D) fp16
    dim3 gA(S_LEN / 256, BATCH * NHEADS);
    attn_f16_kernel<<<gA, 256, ATTN_SMEM>>>(qp, kp, vp, attp);

    // 3) Output projection (fp16 mma) -> fp32 d_out
    dim3 gO(DMODEL / GTN, M_TOTAL / GTM, 1);
    gemm_f16_kernel<<<gO, 256, GEMM_SMEM>>>(attp, wor, wor, wor,
                                            nullptr, nullptr, nullptr, out, 0);
}

// round 16
// speedup vs baseline: 2.0820x; 1.0101x over previous
#include <cuda_runtime.h>
#include <cuda_fp16.h>
#include <cstdint>

// Problem constants
#define S_LEN    2048
#define DMODEL   1024
#define NHEADS   16
#define DK       64
#define BATCH    2
#define M_TOTAL  (BATCH * S_LEN)   // 4096

// Scratch (allocation-free rule: __device__ globals)
__device__ __half g_q[BATCH * NHEADS * S_LEN * DK];    // (B,H,S,dk) fp16, pre-scaled
__device__ __half g_k[BATCH * NHEADS * S_LEN * DK];
__device__ __half g_v[BATCH * NHEADS * S_LEN * DK];
__device__ __half g_att[BATCH * S_LEN * DMODEL];       // (B,S,D) fp16
__device__ __half g_half[8 * 1024 * 1024];             // fp16 x + 4 weights

// Q pre-scale folded into QKV epilogue: (1/sqrt(dk)) * log2(e)
#define QSCALE 0.1803368801f

// ---------------------------------------------------------------------------
// Helpers
// ---------------------------------------------------------------------------
__device__ __forceinline__ uint32_t smem_u32(const void* p) {
    uint32_t a;
    asm("{ .reg .u64 t; cvta.to.shared.u64 t, %1; cvt.u32.u64 %0, t; }"
        : "=r"(a) : "l"(p));
    return a;
}

__device__ __forceinline__ void cp_async16(uint32_t s, const void* g) {
    asm volatile("cp.async.cg.shared.global [%0], [%1], 16;" :: "r"(s), "l"(g));
}
#define CP_COMMIT() asm volatile("cp.async.commit_group;" ::: "memory")
#define CP_WAIT(n)  asm volatile("cp.async.wait_group %0;" :: "n"(n) : "memory")

// D(16x8) += A(16x16,row) * B(16x8,col) -- fp16 operands, fp32 accum
__device__ __forceinline__ void mma_f16(float* d,
                                        uint32_t a0, uint32_t a1, uint32_t a2, uint32_t a3,
                                        uint32_t b0, uint32_t b1) {
    asm volatile(
        "mma.sync.aligned.m16n8k16.row.col.f32.f16.f16.f32 "
        "{%0,%1,%2,%3}, {%4,%5,%6,%7}, {%8,%9}, {%0,%1,%2,%3};"
        : "+f"(d[0]), "+f"(d[1]), "+f"(d[2]), "+f"(d[3])
        : "r"(a0), "r"(a1), "r"(a2), "r"(a3), "r"(b0), "r"(b1));
}

__device__ __forceinline__ void ldsm4(uint32_t* r, uint32_t addr) {
    asm volatile("ldmatrix.sync.aligned.m8n8.x4.shared.b16 {%0,%1,%2,%3}, [%4];"
        : "=r"(r[0]), "=r"(r[1]), "=r"(r[2]), "=r"(r[3]) : "r"(addr));
}

__device__ __forceinline__ void ldsm4t(uint32_t* r, uint32_t addr) {
    asm volatile("ldmatrix.sync.aligned.m8n8.x4.trans.shared.b16 {%0,%1,%2,%3}, [%4];"
        : "=r"(r[0]), "=r"(r[1]), "=r"(r[2]), "=r"(r[3]) : "r"(addr));
}

__device__ __forceinline__ uint32_t packh2(float lo, float hi) {
    __half2 h = __floats2half2_rn(lo, hi);
    return *(uint32_t*)&h;
}

__device__ __forceinline__ float ex2f(float x) {
    float r;
    asm("ex2.approx.f32 %0, %1;" : "=f"(r) : "f"(x));
    return r;
}

// ---------------------------------------------------------------------------
// fp32 -> fp16 conversion pass over x + 4 weights. 8 floats per thread.
// ---------------------------------------------------------------------------
__global__ __launch_bounds__(256) void tohalf_kernel(
    const float* __restrict__ x,
    const float* __restrict__ wq, const float* __restrict__ wk,
    const float* __restrict__ wv, const float* __restrict__ wo,
    __half* __restrict__ xr,
    __half* __restrict__ wqr, __half* __restrict__ wkr,
    __half* __restrict__ wvr, __half* __restrict__ wor)
{
    const int bidx = blockIdx.x;
    const float* src;
    __half* dst;
    int off;
    if (bidx < 2048) { src = x; dst = xr; off = bidx; }
    else {
        const int i = (bidx - 2048) >> 9;
        off = (bidx - 2048) & 511;
        src = (i == 0) ? wq : (i == 1) ? wk : (i == 2) ? wv : wo;
        dst = (i == 0) ? wqr : (i == 1) ? wkr : (i == 2) ? wvr : wor;
    }
    const int base = off * 2048 + threadIdx.x * 8;
    float4 v0 = *(const float4*)(src + base);
    float4 v1 = *(const float4*)(src + base + 4);
    uint4 o;
    o.x = packh2(v0.x, v0.y); o.y = packh2(v0.z, v0.w);
    o.z = packh2(v1.x, v1.y); o.w = packh2(v1.z, v1.w);
    *(uint4*)(dst + base) = o;
}

// ---------------------------------------------------------------------------
// fp16 mma.sync GEMM (unchanged from round 15): tile 256x128, warp 64x64.
// K-chunk 128 halfs as two 128B-row swizzled panels; 2 stages = 192KB.
// ---------------------------------------------------------------------------
#define GTM 256
#define GTN 128
#define GCHUNK 128
#define A_PANEL_H (GTM * 64)                  // 16384 halfs = 32KB
#define B_PANEL_H (GTN * 64)                  // 8192 halfs = 16KB
#define A_STG_H (2 * A_PANEL_H)               // 64KB
#define B_STG_H (2 * B_PANEL_H)               // 32KB
#define STG_H   (A_STG_H + B_STG_H)           // 49152 halfs = 96KB
#define GSTAGES 2
#define GEMM_SMEM (GSTAGES * STG_H * 2)       // 196608 B

__global__ __launch_bounds__(256, 1) void gemm_f16_kernel(
    const __half* __restrict__ A,
    const __half* __restrict__ W0, const __half* __restrict__ W1, const __half* __restrict__ W2,
    __half* __restrict__ C0, __half* __restrict__ C1, __half* __restrict__ C2,
    float* __restrict__ CF, int scatter)
{
    const __half* __restrict__ W = (blockIdx.z == 0) ? W0 : (blockIdx.z == 1) ? W1 : W2;
    __half* __restrict__ C       = (blockIdx.z == 0) ? C0 : (blockIdx.z == 1) ? C1 : C2;

    extern __shared__ __half smh[];

    const int tid  = threadIdx.x;
    const int wid  = tid >> 5;
    const int lane = tid & 31;
    const int g    = lane >> 2;
    const int t    = lane & 3;
    const int wm   = wid & 3;
    const int wn   = wid >> 2;
    const int nBase = blockIdx.x * GTN;
    const int mBase = blockIdx.y * GTM;

    float acc[4][8][4];
#pragma unroll
    for (int i = 0; i < 4; i++)
#pragma unroll
        for (int j = 0; j < 8; j++)
#pragma unroll
            for (int l = 0; l < 4; l++) acc[i][j][l] = 0.0f;

    const uint32_t smemA0 = smem_u32(smh);

    const int rowA = wm * 64 + (lane & 15);
    const int rowB = wn * 64 + (lane & 7) + ((lane >> 4) << 3);
    const int c4bitA = lane >> 4;
    const int c4bitB = (lane >> 3) & 1;
    const int lxor   = lane & 7;

    auto issue = [&](int c, int s) {
        const uint32_t st = smemA0 + (uint32_t)(s * STG_H) * 2u;
#pragma unroll
        for (int i = 0; i < 16; i++) {
            const int idx = tid + 256 * i;
            const int r = idx >> 4, cg = idx & 15;
            const int pan = cg >> 3, c8 = cg & 7;
            const uint32_t off =
                (uint32_t)(pan * A_PANEL_H * 2 + r * 128 + (((c8 ^ (r & 7)) & 7) << 4));
            cp_async16(st + off, A + (size_t)(mBase + r) * DMODEL + c * GCHUNK + cg * 8);
        }
#pragma unroll
        for (int i = 0; i < 8; i++) {
            const int idx = tid + 256 * i;
            const int r = idx >> 4, cg = idx & 15;
            const int pan = cg >> 3, c8 = cg & 7;
            const uint32_t off =
                (uint32_t)(pan * B_PANEL_H * 2 + r * 128 + (((c8 ^ (r & 7)) & 7) << 4));
            cp_async16(st + (uint32_t)A_STG_H * 2u + off,
                       W + (size_t)(nBase + r) * DMODEL + c * GCHUNK + cg * 8);
        }
    };

    issue(0, 0); CP_COMMIT();

    const int NCHUNK = DMODEL / GCHUNK;   // 8
    for (int c = 0; c < NCHUNK; c++) {
        CP_WAIT(0);
        __syncthreads();
        if (c + 1 < NCHUNK) issue(c + 1, (c + 1) & 1);
        CP_COMMIT();

        const uint32_t Ast = smemA0 + (uint32_t)((c & 1) * STG_H) * 2u;
        const uint32_t Bst = Ast + (uint32_t)A_STG_H * 2u;

#pragma unroll
        for (int ks = 0; ks < 8; ks++) {
            const uint32_t panA = (uint32_t)((ks >> 2) * A_PANEL_H) * 2u;
            const uint32_t panB = (uint32_t)((ks >> 2) * B_PANEL_H) * 2u;
            const int k2 = ks & 3;
            const int xa = ((2 * k2 + c4bitA) ^ lxor) & 7;
            const int xb = ((2 * k2 + c4bitB) ^ lxor) & 7;

            uint32_t a[4][4];
#pragma unroll
            for (int mt = 0; mt < 4; mt++)
                ldsm4(a[mt], Ast + panA + (uint32_t)((rowA + mt * 16) * 128 + xa * 16));

            uint32_t b[4][4];
#pragma unroll
            for (int ntp = 0; ntp < 4; ntp++)
                ldsm4(b[ntp], Bst + panB + (uint32_t)((rowB + ntp * 16) * 128 + xb * 16));

#pragma unroll
            for (int mt = 0; mt < 4; mt++)
#pragma unroll
                for (int ntp = 0; ntp < 4; ntp++) {
                    mma_f16(acc[mt][2 * ntp],     a[mt][0], a[mt][1], a[mt][2], a[mt][3],
                            b[ntp][0], b[ntp][1]);
                    mma_f16(acc[mt][2 * ntp + 1], a[mt][0], a[mt][1], a[mt][2], a[mt][3],
                            b[ntp][2], b[ntp][3]);
                }
        }
    }

    const float qs = (scatter && blockIdx.z == 0) ? QSCALE : 1.0f;
#pragma unroll
    for (int mt = 0; mt < 4; mt++) {
#pragma unroll
        for (int half = 0; half < 2; half++) {
            const int m = mBase + wm * 64 + mt * 16 + g + half * 8;
#pragma unroll
            for (int nt = 0; nt < 8; nt++) {
                const int n = nBase + wn * 64 + nt * 8 + 2 * t;
                const float vx = acc[mt][nt][half * 2 + 0];
                const float vy = acc[mt][nt][half * 2 + 1];
                if (scatter) {
                    const int b = m >> 11, s = m & 2047;
                    const int head = n >> 6, d0 = n & 63;
                    const uint32_t u = packh2(vx * qs, vy * qs);
                    *(uint32_t*)&C[(((size_t)((b << 4) + head) * S_LEN + s) * DK + d0)] = u;
                } else {
                    float2 v; v.x = vx; v.y = vy;
                    *(float2*)&CF[(size_t)m * DMODEL + n] = v;
                }
            }
        }
    }
}

// ---------------------------------------------------------------------------
// fp16 flash attention. CTA: 256 thr (8 warps), Q block 256 rows (32/warp).
// KV loaded in 128-row tiles (ONE sync per 128 rows), processed as two
// sequential 64-row halves with the validated inner body.
// Q/K frags via ldmatrix on padded 144B rows; exp2-domain softmax;
// P in registers; V via ldmatrix.x4.trans.
// ---------------------------------------------------------------------------
#define AKSTR   72                        // halfs per row (144B)
#define KV_ROWS 128                       // rows per loaded tile
#define K_TILE_H (KV_ROWS * AKSTR)        // 9216 halfs
#define ASTG_H  (2 * K_TILE_H)            // 18432 halfs (K then V)
#define SQ_OFF_H (2 * ASTG_H)             // 36864 halfs
#define SQW_H   (32 * AKSTR)              // 2304 halfs per warp
#define ATTN_SMEM ((SQ_OFF_H + 8 * SQW_H) * 2)   // 110592 B

__global__ __launch_bounds__(256) void attn_f16_kernel(
    const __half* __restrict__ Q, const __half* __restrict__ K,
    const __half* __restrict__ V, __half* __restrict__ Oatt)
{
    extern __shared__ __half smh[];

    const int tid  = threadIdx.x;
    const int wid  = tid >> 5;
    const int lane = tid & 31;
    const int g    = lane >> 2;
    const int t    = lane & 3;
    const int qb   = blockIdx.x;            // 0..7
    const int bh   = blockIdx.y;            // 0..31
    const int b    = bh >> 4;
    const int h    = bh & 15;

    const uint32_t smemB = smem_u32(smh);
    const uint32_t sqwB  = smemB + (uint32_t)(SQ_OFF_H + wid * SQW_H) * 2u;
    __half* sQw = smh + SQ_OFF_H + wid * SQW_H;

    // ---- Stage Q slice (32 rows/warp) into padded rows (already scaled)
    {
        const __half* Qg = Q + ((size_t)bh * S_LEN + qb * 256 + wid * 32) * DK;
#pragma unroll
        for (int i = 0; i < 8; i++) {
            const int idx = lane + 32 * i;
            const int r = idx >> 3, cg = idx & 7;
            *(uint4*)(sQw + r * AKSTR + cg * 8) = *(const uint4*)(Qg + r * DK + cg * 8);
        }
        __syncwarp();
    }

    float o_[2][8][4];
#pragma unroll
    for (int mt = 0; mt < 2; mt++)
#pragma unroll
        for (int nt = 0; nt < 8; nt++)
#pragma unroll
            for (int l = 0; l < 4; l++) o_[mt][nt][l] = 0.0f;
    float mrow[2][2] = {{-1e30f, -1e30f}, {-1e30f, -1e30f}};
    float lrow[2][2] = {{0.0f, 0.0f}, {0.0f, 0.0f}};

    const __half* Kg = K + (size_t)bh * S_LEN * DK;
    const __half* Vg = V + (size_t)bh * S_LEN * DK;

    // 128-row K/V tile loader: 1024 K-groups + 1024 V-groups, 8/thread
    auto issue = [&](int kv2, int st) {
        const uint32_t stb = smemB + (uint32_t)(st * ASTG_H) * 2u;
        const __half* kS = Kg + (size_t)kv2 * KV_ROWS * DK;
        const __half* vS = Vg + (size_t)kv2 * KV_ROWS * DK;
#pragma unroll
        for (int i = 0; i < 4; i++) {
            const int idx = tid + 256 * i;      // 0..1023
            const int r = idx >> 3, cg = idx & 7;
            cp_async16(stb + (uint32_t)(r * 144 + cg * 16), kS + r * DK + cg * 8);
            cp_async16(stb + (uint32_t)K_TILE_H * 2u + (uint32_t)(r * 144 + cg * 16),
                       vS + r * DK + cg * 8);
        }
    };

    issue(0, 0); CP_COMMIT();

    // ldmatrix lane bases
    const uint32_t qoff = (uint32_t)((lane & 15) * 144 + ((lane >> 4) << 4));
    const uint32_t koff = (uint32_t)(((lane & 7) + ((lane >> 4) << 3)) * 144
                                     + (((lane >> 3) & 1) << 4));

    const int NKV2 = S_LEN / KV_ROWS;   // 16
    for (int kv2 = 0; kv2 < NKV2; kv2++) {
        CP_WAIT(0);
        __syncthreads();
        if (kv2 + 1 < NKV2) issue(kv2 + 1, (kv2 + 1) & 1);
        CP_COMMIT();

        const uint32_t Tst = smemB + (uint32_t)((kv2 & 1) * ASTG_H) * 2u;

#pragma unroll
        for (int half = 0; half < 2; half++) {
            const uint32_t Kst   = Tst + (uint32_t)(half * 64 * 144);
            const uint32_t Vbase = Tst + (uint32_t)K_TILE_H * 2u + (uint32_t)(half * 64 * 144);

            // ---- scores S = Q' K^T (log2 domain), 32x64/warp
            float s_[2][8][4];
#pragma unroll
            for (int mt = 0; mt < 2; mt++)
#pragma unroll
                for (int nt = 0; nt < 8; nt++)
#pragma unroll
                    for (int l = 0; l < 4; l++) s_[mt][nt][l] = 0.0f;

#pragma unroll
            for (int ks = 0; ks < 4; ks++) {
                uint32_t a[2][4];
                ldsm4(a[0], sqwB + qoff + (uint32_t)(ks * 32));
                ldsm4(a[1], sqwB + qoff + (uint32_t)(16 * 144 + ks * 32));
                uint32_t bb[4][4];
#pragma unroll
                for (int ntp = 0; ntp < 4; ntp++)
                    ldsm4(bb[ntp], Kst + koff + (uint32_t)(ntp * 16 * 144 + ks * 32));
#pragma unroll
                for (int ntp = 0; ntp < 4; ntp++) {
                    mma_f16(s_[0][2 * ntp],     a[0][0], a[0][1], a[0][2], a[0][3],
                            bb[ntp][0], bb[ntp][1]);
                    mma_f16(s_[0][2 * ntp + 1], a[0][0], a[0][1], a[0][2], a[0][3],
                            bb[ntp][2], bb[ntp][3]);
                    mma_f16(s_[1][2 * ntp],     a[1][0], a[1][1], a[1][2], a[1][3],
                            bb[ntp][0], bb[ntp][1]);
                    mma_f16(s_[1][2 * ntp + 1], a[1][0], a[1][1], a[1][2], a[1][3],
                            bb[ntp][2], bb[ntp][3]);
                }
            }

            // ---- online softmax per m-tile (exp2 domain, fp32)
#pragma unroll
            for (int mt = 0; mt < 2; mt++) {
                float mx0 = -1e30f, mx1 = -1e30f;
#pragma unroll
                for (int nt = 0; nt < 8; nt++) {
                    mx0 = fmaxf(mx0, fmaxf(s_[mt][nt][0], s_[mt][nt][1]));
                    mx1 = fmaxf(mx1, fmaxf(s_[mt][nt][2], s_[mt][nt][3]));
                }
                mx0 = fmaxf(mx0, __shfl_xor_sync(0xffffffffu, mx0, 1));
                mx0 = fmaxf(mx0, __shfl_xor_sync(0xffffffffu, mx0, 2));
                mx1 = fmaxf(mx1, __shfl_xor_sync(0xffffffffu, mx1, 1));
                mx1 = fmaxf(mx1, __shfl_xor_sync(0xffffffffu, mx1, 2));

                float mn0 = fmaxf(mrow[mt][0], mx0), mn1 = fmaxf(mrow[mt][1], mx1);
                float al0 = ex2f(mrow[mt][0] - mn0), al1 = ex2f(mrow[mt][1] - mn1);
                mrow[mt][0] = mn0; mrow[mt][1] = mn1;

                float s0 = 0.0f, s1 = 0.0f;
#pragma unroll
                for (int nt = 0; nt < 8; nt++) {
                    s_[mt][nt][0] = ex2f(s_[mt][nt][0] - mn0); s0 += s_[mt][nt][0];
                    s_[mt][nt][1] = ex2f(s_[mt][nt][1] - mn0); s0 += s_[mt][nt][1];
                    s_[mt][nt][2] = ex2f(s_[mt][nt][2] - mn1); s1 += s_[mt][nt][2];
                    s_[mt][nt][3] = ex2f(s_[mt][nt][3] - mn1); s1 += s_[mt][nt][3];
                }
                s0 += __shfl_xor_sync(0xffffffffu, s0, 1);
                s0 += __shfl_xor_sync(0xffffffffu, s0, 2);
                s1 += __shfl_xor_sync(0xffffffffu, s1, 1);
                s1 += __shfl_xor_sync(0xffffffffu, s1, 2);
                lrow[mt][0] = lrow[mt][0] * al0 + s0;
                lrow[mt][1] = lrow[mt][1] * al1 + s1;

#pragma unroll
                for (int nt = 0; nt < 8; nt++) {
                    o_[mt][nt][0] *= al0; o_[mt][nt][1] *= al0;
                    o_[mt][nt][2] *= al1; o_[mt][nt][3] *= al1;
                }
            }

            // ---- O += P V : P packed reg->reg, V b-frags via ldmatrix.trans
#pragma unroll
            for (int kt = 0; kt < 4; kt++) {
                uint32_t ap[2][4];
#pragma unroll
                for (int mt = 0; mt < 2; mt++) {
                    ap[mt][0] = packh2(s_[mt][2 * kt][0],     s_[mt][2 * kt][1]);
                    ap[mt][1] = packh2(s_[mt][2 * kt][2],     s_[mt][2 * kt][3]);
                    ap[mt][2] = packh2(s_[mt][2 * kt + 1][0], s_[mt][2 * kt + 1][1]);
                    ap[mt][3] = packh2(s_[mt][2 * kt + 1][2], s_[mt][2 * kt + 1][3]);
                }
                const int kvrow = kt * 16 + (lane & 15);
#pragma unroll
                for (int ntp = 0; ntp < 4; ntp++) {
                    const int colb = ntp * 16 + ((lane >> 4) << 3);
                    uint32_t vv[4];
                    ldsm4t(vv, Vbase + (uint32_t)(kvrow * 144 + colb * 2));
                    mma_f16(o_[0][2 * ntp],     ap[0][0], ap[0][1], ap[0][2], ap[0][3], vv[0], vv[1]);
                    mma_f16(o_[0][2 * ntp + 1], ap[0][0], ap[0][1], ap[0][2], ap[0][3], vv[2], vv[3]);
                    mma_f16(o_[1][2 * ntp],     ap[1][0], ap[1][1], ap[1][2], ap[1][3], vv[0], vv[1]);
                    mma_f16(o_[1][2 * ntp + 1], ap[1][0], ap[1][1], ap[1][2], ap[1][3], vv[2], vv[3]);
                }
            }
        }
    }

    // ---- epilogue: normalize, write fp16 (B,S,D)
#pragma unroll
    for (int mt = 0; mt < 2; mt++) {
        const float inv0 = 1.0f / lrow[mt][0], inv1 = 1.0f / lrow[mt][1];
        const int row0 = qb * 256 + wid * 32 + mt * 16 + g;
#pragma unroll
        for (int nt = 0; nt < 8; nt++) {
            const int col = h * DK + nt * 8 + 2 * t;
            const uint32_t u0 = packh2(o_[mt][nt][0] * inv0, o_[mt][nt][1] * inv0);
            const uint32_t u1 = packh2(o_[mt][nt][2] * inv1, o_[mt][nt][3] * inv1);
            *(uint32_t*)&Oatt[((size_t)b * S_LEN + row0) * DMODEL + col]     = u0;
            *(uint32_t*)&Oatt[((size_t)b * S_LEN + row0 + 8) * DMODEL + col] = u1;
        }
    }
}

// ---------------------------------------------------------------------------
extern "C" void kernel_launch(void* const* d_in, const int* in_sizes, int n_in,
                              void* d_out, int out_size)
{
    const float* x  = (const float*)d_in[0];
    const float* Wq = (const float*)d_in[1];
    const float* Wk = (const float*)d_in[2];
    const float* Wv = (const float*)d_in[3];
    const float* Wo = (const float*)d_in[4];
    float* out = (float*)d_out;

    __half *qp, *kp, *vp, *attp, *hp;
    cudaGetSymbolAddress((void**)&qp,   g_q);
    cudaGetSymbolAddress((void**)&kp,   g_k);
    cudaGetSymbolAddress((void**)&vp,   g_v);
    cudaGetSymbolAddress((void**)&attp, g_att);
    cudaGetSymbolAddress((void**)&hp,   g_half);

    __half* xr  = hp;
    __half* wqr = hp + 4 * 1024 * 1024;
    __half* wkr = hp + 5 * 1024 * 1024;
    __half* wvr = hp + 6 * 1024 * 1024;
    __half* wor = hp + 7 * 1024 * 1024;

    // 0) fp32 -> fp16 conversion of all GEMM operands
    tohalf_kernel<<<4096, 256>>>(x, Wq, Wk, Wv, Wo, xr, wqr, wkr, wvr, wor);

    cudaFuncSetAttribute(gemm_f16_kernel, cudaFuncAttributeMaxDynamicSharedMemorySize,
                         GEMM_SMEM);
    cudaFuncSetAttribute(attn_f16_kernel, cudaFuncAttributeMaxDynamicSharedMemorySize,
                         ATTN_SMEM);

    // 1) Fused QKV projections (fp16 mma), scatter to (B,H,S,dk); Q pre-scaled
    dim3 gQKV(DMODEL / GTN, M_TOTAL / GTM, 3);
    gemm_f16_kernel<<<gQKV, 256, GEMM_SMEM>>>(xr, wqr, wkr, wvr, qp, kp, vp,
                                              nullptr, 1);

    // 2) Flash attention (fp16 mma, exp2 softmax) -> (B,S,D) fp16
    dim3 gA(S_LEN / 256, BATCH * NHEADS);
    attn_f16_kernel<<<gA, 256, ATTN_SMEM>>>(qp, kp, vp, attp);

    // 3) Output projection (fp16 mma) -> fp32 d_out
    dim3 gO(DMODEL / GTN, M_TOTAL / GTM, 1);
    gemm_f16_kernel<<<gO, 256, GEMM_SMEM>>>(attp, wor, wor, wor,
                                            nullptr, nullptr, nullptr, out, 0);
}